// round 1
// baseline (speedup 1.0000x reference)
#include <cuda_runtime.h>

#define NV 100000
#define EE 1600000
#define BB 64
#define HIDDEN 128
#define DMODEL 256
#define EPSV 1e-5f
#define POOL_ROWS 128

// ---------------- scratch (static device globals; no allocation) ----------------
__device__ float g_h[NV * HIDDEN];     // pre-aggregation features h = x @ W
__device__ float g_bufA[NV * HIDDEN];  // ping
__device__ float g_bufB[NV * HIDDEN];  // pong
__device__ float g_dinv[NV];           // deg -> deg^{-1/2}
__device__ float g_summ[BB * HIDDEN];  // pooled sums
__device__ float g_cnt[BB];            // pooled counts

// ---------------- kernels ----------------
__global__ void zero_kernel() {
    int i = blockIdx.x * blockDim.x + threadIdx.x;
    if (i < NV) g_dinv[i] = 0.f;
    if (i < BB * HIDDEN) g_summ[i] = 0.f;
    if (i < BB) g_cnt[i] = 0.f;
}

__global__ void deg_kernel(const int* __restrict__ dst) {
    int e = blockIdx.x * blockDim.x + threadIdx.x;
    if (e < EE) atomicAdd(&g_dinv[dst[e]], 1.f);
}

__global__ void dinv_kernel() {
    int i = blockIdx.x * blockDim.x + threadIdx.x;
    if (i < NV) g_dinv[i] = rsqrtf(g_dinv[i] + 1.f);
}

// x0 = vertices @ W_in + b_in  -> g_bufA.  One warp-slot thread per (row, 4 cols).
__global__ void input_kernel(const float* __restrict__ v,
                             const float* __restrict__ Wi,
                             const float* __restrict__ bi) {
    int t = blockIdx.x * blockDim.x + threadIdx.x;
    int row = t >> 5, q = t & 31;
    if (row >= NV) return;
    float v0 = v[row * 3 + 0], v1 = v[row * 3 + 1], v2 = v[row * 3 + 2];
    int c = q * 4;
    float4 o;
    float* po = &o.x;
#pragma unroll
    for (int j = 0; j < 4; j++) {
        int cc = c + j;
        po[j] = bi[cc] + v0 * Wi[cc] + v1 * Wi[HIDDEN + cc] + v2 * Wi[2 * HIDDEN + cc];
    }
    *((float4*)g_bufA + row * 32 + q) = o;
}

// H = act(X) @ W ;  AGG = H*dinv^2 + bias  (self-loop + bias fused).
// Tile: 64 rows x 128 cols per block, 256 threads, 4x8 register tile.
template <bool RELU>
__global__ void gemm_kernel(const float* __restrict__ X,
                            const float* __restrict__ W,
                            const float* __restrict__ bias,
                            float* __restrict__ H,
                            float* __restrict__ AGG) {
    extern __shared__ float sm[];
    float* Ws = sm;                    // 128*128
    float* Xs = sm + HIDDEN * HIDDEN;  // 64 rows * stride 132
    const int XST = 132;
    int t = threadIdx.x;
    int row0 = blockIdx.x * 64;

#pragma unroll
    for (int i = 0; i < 16; i++) {
        int idx = (i * 256 + t) * 4;
        *(float4*)(Ws + idx) = *(const float4*)(W + idx);
    }
#pragma unroll
    for (int i = 0; i < 8; i++) {
        int lin = (i * 256 + t) * 4;
        int r = lin >> 7, k = lin & 127;
        int gr = row0 + r;
        float4 val = make_float4(0.f, 0.f, 0.f, 0.f);
        if (gr < NV) {
            val = *(const float4*)(X + gr * HIDDEN + k);
            if (RELU) {
                val.x = fmaxf(val.x, 0.f); val.y = fmaxf(val.y, 0.f);
                val.z = fmaxf(val.z, 0.f); val.w = fmaxf(val.w, 0.f);
            }
        }
        *(float4*)(Xs + r * XST + k) = val;
    }
    __syncthreads();

    int tx = t & 15, ty = t >> 4;
    int c0 = tx * 8, r0 = ty * 4;
    float acc[4][8];
#pragma unroll
    for (int i = 0; i < 4; i++)
#pragma unroll
        for (int j = 0; j < 8; j++) acc[i][j] = 0.f;

#pragma unroll 8
    for (int k = 0; k < HIDDEN; k++) {
        float4 w0 = *(float4*)(Ws + k * HIDDEN + c0);
        float4 w1 = *(float4*)(Ws + k * HIDDEN + c0 + 4);
        float xv[4];
#pragma unroll
        for (int i = 0; i < 4; i++) xv[i] = Xs[(r0 + i) * XST + k];
#pragma unroll
        for (int i = 0; i < 4; i++) {
            acc[i][0] += xv[i] * w0.x; acc[i][1] += xv[i] * w0.y;
            acc[i][2] += xv[i] * w0.z; acc[i][3] += xv[i] * w0.w;
            acc[i][4] += xv[i] * w1.x; acc[i][5] += xv[i] * w1.y;
            acc[i][6] += xv[i] * w1.z; acc[i][7] += xv[i] * w1.w;
        }
    }

    float4 bv0 = *(const float4*)(bias + c0);
    float4 bv1 = *(const float4*)(bias + c0 + 4);
#pragma unroll
    for (int i = 0; i < 4; i++) {
        int gr = row0 + r0 + i;
        if (gr >= NV) continue;
        float d = g_dinv[gr];
        float d2 = d * d;
        float4 h0 = make_float4(acc[i][0], acc[i][1], acc[i][2], acc[i][3]);
        float4 h1 = make_float4(acc[i][4], acc[i][5], acc[i][6], acc[i][7]);
        *(float4*)(H + gr * HIDDEN + c0) = h0;
        *(float4*)(H + gr * HIDDEN + c0 + 4) = h1;
        float4 a0 = make_float4(h0.x * d2 + bv0.x, h0.y * d2 + bv0.y,
                                h0.z * d2 + bv0.z, h0.w * d2 + bv0.w);
        float4 a1 = make_float4(h1.x * d2 + bv1.x, h1.y * d2 + bv1.y,
                                h1.z * d2 + bv1.z, h1.w * d2 + bv1.w);
        *(float4*)(AGG + gr * HIDDEN + c0) = a0;
        *(float4*)(AGG + gr * HIDDEN + c0 + 4) = a1;
    }
}

// One warp per edge; lane l handles 4 columns via float4 gather + 4 scalar atomics.
__global__ void scatter_kernel(const int* __restrict__ src, const int* __restrict__ dst,
                               float* __restrict__ AGG) {
    long long t = (long long)blockIdx.x * blockDim.x + threadIdx.x;
    int e = (int)(t >> 5), lane = (int)(t & 31);
    if (e >= EE) return;
    int s = src[e], d = dst[e];
    float w = g_dinv[s] * g_dinv[d];
    float4 v = *((const float4*)g_h + s * 32 + lane);
    float* a = AGG + (long long)d * HIDDEN + lane * 4;
    atomicAdd(a + 0, v.x * w);
    atomicAdd(a + 1, v.y * w);
    atomicAdd(a + 2, v.z * w);
    atomicAdd(a + 3, v.w * w);
}

// Segment sum over sorted batch, one thread per column, running-sum + rare atomic flush.
__global__ void pool_kernel(const float* __restrict__ X, const int* __restrict__ batch) {
    int c = threadIdx.x;
    int row0 = blockIdx.x * POOL_ROWS;
    if (row0 >= NV) return;
    int rend = min(row0 + POOL_ROWS, NV);
    float acc = 0.f;
    int cur = batch[row0];
    int runstart = row0;
    for (int r = row0; r < rend; r++) {
        int b = batch[r];
        if (b != cur) {
            atomicAdd(&g_summ[cur * HIDDEN + c], acc);
            if (c == 0) atomicAdd(&g_cnt[cur], (float)(r - runstart));
            acc = 0.f; cur = b; runstart = r;
        }
        acc += fmaxf(X[(long long)r * HIDDEN + c], 0.f);
    }
    atomicAdd(&g_summ[cur * HIDDEN + c], acc);
    if (c == 0) atomicAdd(&g_cnt[cur], (float)(rend - runstart));
}

// pooled = summ/cnt ; y = pooled @ W_out + b_out ; layernorm -> out
__global__ void final_kernel(const float* __restrict__ Wo, const float* __restrict__ bo,
                             const float* __restrict__ gamma, const float* __restrict__ beta,
                             float* __restrict__ out) {
    __shared__ float p[HIDDEN];
    __shared__ float rs[DMODEL];
    __shared__ float rq[DMODEL];
    int b = blockIdx.x, c = threadIdx.x;
    if (c < HIDDEN) {
        float cnt = fmaxf(g_cnt[b], 1.f);
        p[c] = g_summ[b * HIDDEN + c] / cnt;
    }
    __syncthreads();
    float y = bo[c];
#pragma unroll 8
    for (int k = 0; k < HIDDEN; k++) y += p[k] * Wo[k * DMODEL + c];
    rs[c] = y;
    rq[c] = y * y;
    __syncthreads();
    for (int s = DMODEL / 2; s > 0; s >>= 1) {
        if (c < s) { rs[c] += rs[c + s]; rq[c] += rq[c + s]; }
        __syncthreads();
    }
    float mu = rs[0] / (float)DMODEL;
    float var = rq[0] / (float)DMODEL - mu * mu;
    out[b * DMODEL + c] = (y - mu) * rsqrtf(var + EPSV) * gamma[c] + beta[c];
}

// ---------------- launch ----------------
extern "C" void kernel_launch(void* const* d_in, const int* in_sizes, int n_in,
                              void* d_out, int out_size) {
    const float* vertices = (const float*)d_in[0];
    const int*   eidx     = (const int*)d_in[1];
    const int*   batch    = (const int*)d_in[2];
    const float* W_in     = (const float*)d_in[3];
    const float* b_in     = (const float*)d_in[4];
    const float* W1       = (const float*)d_in[5];
    const float* b1       = (const float*)d_in[6];
    const float* W2       = (const float*)d_in[7];
    const float* b2       = (const float*)d_in[8];
    const float* W3       = (const float*)d_in[9];
    const float* b3       = (const float*)d_in[10];
    const float* W_out    = (const float*)d_in[11];
    const float* b_out    = (const float*)d_in[12];
    const float* gamma    = (const float*)d_in[13];
    const float* beta     = (const float*)d_in[14];
    const int* src = eidx;
    const int* dst = eidx + EE;
    float* out = (float*)d_out;

    float *ph, *pA, *pB;
    cudaGetSymbolAddress((void**)&ph, g_h);
    cudaGetSymbolAddress((void**)&pA, g_bufA);
    cudaGetSymbolAddress((void**)&pB, g_bufB);

    size_t smem = (HIDDEN * HIDDEN + 64 * 132) * sizeof(float);  // ~97.6 KB
    cudaFuncSetAttribute(gemm_kernel<false>, cudaFuncAttributeMaxDynamicSharedMemorySize, (int)smem);
    cudaFuncSetAttribute(gemm_kernel<true>,  cudaFuncAttributeMaxDynamicSharedMemorySize, (int)smem);

    zero_kernel<<<(NV + 255) / 256, 256>>>();
    deg_kernel<<<(EE + 255) / 256, 256>>>(dst);
    dinv_kernel<<<(NV + 255) / 256, 256>>>();
    input_kernel<<<(NV * 32 + 255) / 256, 256>>>(vertices, W_in, b_in);

    int gblocks = (NV + 63) / 64;
    int sblocks = (int)(((long long)EE * 32 + 255) / 256);

    gemm_kernel<false><<<gblocks, 256, smem>>>(pA, W1, b1, ph, pB);
    scatter_kernel<<<sblocks, 256>>>(src, dst, pB);

    gemm_kernel<true><<<gblocks, 256, smem>>>(pB, W2, b2, ph, pA);
    scatter_kernel<<<sblocks, 256>>>(src, dst, pA);

    gemm_kernel<true><<<gblocks, 256, smem>>>(pA, W3, b3, ph, pB);
    scatter_kernel<<<sblocks, 256>>>(src, dst, pB);

    pool_kernel<<<(NV + POOL_ROWS - 1) / POOL_ROWS, HIDDEN>>>(pB, batch);
    final_kernel<<<BB, DMODEL>>>(W_out, b_out, gamma, beta, out);
}

// round 2
// speedup vs baseline: 2.6766x; 2.6766x over previous
#include <cuda_runtime.h>

#define NV 100000
#define EE 1600000
#define BB 64
#define HIDDEN 128
#define DMODEL 256
#define EPSV 1e-5f
#define POOL_ROWS 128
#define NBLK ((NV + 255) / 256)   // 391 scan blocks

// ---------------- scratch (static device globals; no allocation) ----------------
__device__ float g_h[NV * HIDDEN];      // pre-aggregation features h = x @ W
__device__ float g_bufA[NV * HIDDEN];   // ping
__device__ float g_bufB[NV * HIDDEN];   // pong
__device__ float g_dinv[NV];            // deg^{-1/2}
__device__ int   g_deg[NV];             // in-degree
__device__ int   g_rowptr[NV + 1];      // CSR offsets (by dst)
__device__ int   g_pos[NV];             // running insert positions for sort
__device__ int   g_bsum[NBLK];          // block partial sums for scan
__device__ int2  g_epack[EE];           // sorted edges: {src, bits(w)}
__device__ float g_summ[BB * HIDDEN];   // pooled sums
__device__ float g_cnt[BB];             // pooled counts

// ---------------- setup kernels ----------------
__global__ void zero_kernel() {
    int i = blockIdx.x * blockDim.x + threadIdx.x;
    if (i < NV) g_deg[i] = 0;
    if (i < BB * HIDDEN) g_summ[i] = 0.f;
    if (i < BB) g_cnt[i] = 0.f;
}

__global__ void deg_kernel(const int* __restrict__ dst) {
    int e = blockIdx.x * blockDim.x + threadIdx.x;
    if (e < EE) atomicAdd(&g_deg[dst[e]], 1);
}

__global__ void dinv_kernel() {
    int i = blockIdx.x * blockDim.x + threadIdx.x;
    if (i < NV) g_dinv[i] = rsqrtf((float)g_deg[i] + 1.f);
}

// --- two-level exclusive scan of g_deg -> g_rowptr / g_pos ---
__global__ void blocksum_kernel() {
    __shared__ int s[256];
    int tid = threadIdx.x;
    int i = blockIdx.x * 256 + tid;
    int v = (i < NV) ? g_deg[i] : 0;
    s[tid] = v;
    __syncthreads();
#pragma unroll
    for (int st = 128; st > 0; st >>= 1) {
        if (tid < st) s[tid] += s[tid + st];
        __syncthreads();
    }
    if (tid == 0) g_bsum[blockIdx.x] = s[0];
}

__global__ void scanbsum_kernel() {  // single block, 512 threads, NBLK <= 512
    __shared__ int s[512];
    int tid = threadIdx.x;
    int v = (tid < NBLK) ? g_bsum[tid] : 0;
    s[tid] = v;
    __syncthreads();
#pragma unroll
    for (int off = 1; off < 512; off <<= 1) {
        int t = (tid >= off) ? s[tid - off] : 0;
        __syncthreads();
        s[tid] += t;
        __syncthreads();
    }
    if (tid < NBLK) g_bsum[tid] = s[tid] - v;  // exclusive
}

__global__ void scanfinal_kernel() {
    __shared__ int s[256];
    int tid = threadIdx.x;
    int i = blockIdx.x * 256 + tid;
    int v = (i < NV) ? g_deg[i] : 0;
    s[tid] = v;
    __syncthreads();
#pragma unroll
    for (int off = 1; off < 256; off <<= 1) {
        int t = (tid >= off) ? s[tid - off] : 0;
        __syncthreads();
        s[tid] += t;
        __syncthreads();
    }
    int ex = s[tid] - v + g_bsum[blockIdx.x];
    if (i < NV) { g_rowptr[i] = ex; g_pos[i] = ex; }
    if (i == NV - 1) g_rowptr[NV] = ex + v;
}

// counting-sort edges by dst; pack {src, w} per edge
__global__ void sort_kernel(const int* __restrict__ src, const int* __restrict__ dst) {
    int e = blockIdx.x * blockDim.x + threadIdx.x;
    if (e >= EE) return;
    int s = src[e], d = dst[e];
    int p = atomicAdd(&g_pos[d], 1);
    float w = g_dinv[s] * g_dinv[d];
    g_epack[p] = make_int2(s, __float_as_int(w));
}

// ---------------- input projection: x0 = vertices @ W_in + b_in ----------------
__global__ void input_kernel(const float* __restrict__ v,
                             const float* __restrict__ Wi,
                             const float* __restrict__ bi) {
    __shared__ float sw[3 * HIDDEN + HIDDEN];
    for (int i = threadIdx.x; i < 4 * HIDDEN; i += 256)
        sw[i] = (i < 3 * HIDDEN) ? Wi[i] : bi[i - 3 * HIDDEN];
    __syncthreads();
    int t = blockIdx.x * 256 + threadIdx.x;
    int row = t >> 5, q = t & 31;
    if (row >= NV) return;
    float v0 = v[row * 3 + 0], v1 = v[row * 3 + 1], v2 = v[row * 3 + 2];
    int c = q * 4;
    float4 o;
    float* po = &o.x;
#pragma unroll
    for (int j = 0; j < 4; j++) {
        int cc = c + j;
        po[j] = sw[3 * HIDDEN + cc] + v0 * sw[cc] + v1 * sw[HIDDEN + cc] + v2 * sw[2 * HIDDEN + cc];
    }
    *((float4*)g_bufA + row * 32 + q) = o;
}

// ---------------- H = act(X) @ W  (64x128 tile, 4x8 register tile) ----------------
template <bool RELU>
__global__ void gemm_kernel(const float* __restrict__ X,
                            const float* __restrict__ W,
                            float* __restrict__ H) {
    extern __shared__ float sm[];
    float* Ws = sm;                    // 128*128
    float* Xs = sm + HIDDEN * HIDDEN;  // 64 rows * stride 132
    const int XST = 132;
    int t = threadIdx.x;
    int row0 = blockIdx.x * 64;

#pragma unroll
    for (int i = 0; i < 16; i++) {
        int idx = (i * 256 + t) * 4;
        *(float4*)(Ws + idx) = *(const float4*)(W + idx);
    }
#pragma unroll
    for (int i = 0; i < 8; i++) {
        int lin = (i * 256 + t) * 4;
        int r = lin >> 7, k = lin & 127;
        int gr = row0 + r;
        float4 val = make_float4(0.f, 0.f, 0.f, 0.f);
        if (gr < NV) {
            val = *(const float4*)(X + gr * HIDDEN + k);
            if (RELU) {
                val.x = fmaxf(val.x, 0.f); val.y = fmaxf(val.y, 0.f);
                val.z = fmaxf(val.z, 0.f); val.w = fmaxf(val.w, 0.f);
            }
        }
        *(float4*)(Xs + r * XST + k) = val;
    }
    __syncthreads();

    int tx = t & 15, ty = t >> 4;
    int c0 = tx * 8, r0 = ty * 4;
    float acc[4][8];
#pragma unroll
    for (int i = 0; i < 4; i++)
#pragma unroll
        for (int j = 0; j < 8; j++) acc[i][j] = 0.f;

#pragma unroll 8
    for (int k = 0; k < HIDDEN; k++) {
        float4 w0 = *(float4*)(Ws + k * HIDDEN + c0);
        float4 w1 = *(float4*)(Ws + k * HIDDEN + c0 + 4);
        float xv[4];
#pragma unroll
        for (int i = 0; i < 4; i++) xv[i] = Xs[(r0 + i) * XST + k];
#pragma unroll
        for (int i = 0; i < 4; i++) {
            acc[i][0] += xv[i] * w0.x; acc[i][1] += xv[i] * w0.y;
            acc[i][2] += xv[i] * w0.z; acc[i][3] += xv[i] * w0.w;
            acc[i][4] += xv[i] * w1.x; acc[i][5] += xv[i] * w1.y;
            acc[i][6] += xv[i] * w1.z; acc[i][7] += xv[i] * w1.w;
        }
    }

#pragma unroll
    for (int i = 0; i < 4; i++) {
        int gr = row0 + r0 + i;
        if (gr >= NV) continue;
        *(float4*)(H + gr * HIDDEN + c0) =
            make_float4(acc[i][0], acc[i][1], acc[i][2], acc[i][3]);
        *(float4*)(H + gr * HIDDEN + c0 + 4) =
            make_float4(acc[i][4], acc[i][5], acc[i][6], acc[i][7]);
    }
}

// ---------------- aggregation: one warp per dst row, zero atomics ----------------
// OUT[r] = H[r]*dinv[r]^2 + bias + sum_{e in CSR[r]} w_e * H[src_e]
__global__ void agg_kernel(const float* __restrict__ H,
                           const float* __restrict__ bias,
                           float* __restrict__ OUT) {
    int gw = (blockIdx.x * blockDim.x + threadIdx.x) >> 5;
    int lane = threadIdx.x & 31;
    if (gw >= NV) return;
    int beg = g_rowptr[gw], end = g_rowptr[gw + 1];
    float dd = g_dinv[gw];
    dd *= dd;
    float4 h = *((const float4*)H + gw * 32 + lane);
    float4 b = *((const float4*)bias + lane);
    float4 acc = make_float4(h.x * dd + b.x, h.y * dd + b.y,
                             h.z * dd + b.z, h.w * dd + b.w);

    int e = beg;
    for (; e + 1 < end; e += 2) {   // 2-way unroll for MLP
        int2 p0 = g_epack[e];
        int2 p1 = g_epack[e + 1];
        float w0 = __int_as_float(p0.y);
        float w1 = __int_as_float(p1.y);
        float4 v0 = *((const float4*)H + p0.x * 32 + lane);
        float4 v1 = *((const float4*)H + p1.x * 32 + lane);
        acc.x += w0 * v0.x + w1 * v1.x;
        acc.y += w0 * v0.y + w1 * v1.y;
        acc.z += w0 * v0.z + w1 * v1.z;
        acc.w += w0 * v0.w + w1 * v1.w;
    }
    if (e < end) {
        int2 p = g_epack[e];
        float w = __int_as_float(p.y);
        float4 v = *((const float4*)H + p.x * 32 + lane);
        acc.x += w * v.x; acc.y += w * v.y;
        acc.z += w * v.z; acc.w += w * v.w;
    }
    *((float4*)OUT + gw * 32 + lane) = acc;
}

// ---------------- pooling over sorted batch ----------------
__global__ void pool_kernel(const float* __restrict__ X, const int* __restrict__ batch) {
    int c = threadIdx.x;
    int row0 = blockIdx.x * POOL_ROWS;
    if (row0 >= NV) return;
    int rend = min(row0 + POOL_ROWS, NV);
    float acc = 0.f;
    int cur = batch[row0];
    int runstart = row0;
    for (int r = row0; r < rend; r++) {
        int b = batch[r];
        if (b != cur) {
            atomicAdd(&g_summ[cur * HIDDEN + c], acc);
            if (c == 0) atomicAdd(&g_cnt[cur], (float)(r - runstart));
            acc = 0.f; cur = b; runstart = r;
        }
        acc += fmaxf(X[(long long)r * HIDDEN + c], 0.f);
    }
    atomicAdd(&g_summ[cur * HIDDEN + c], acc);
    if (c == 0) atomicAdd(&g_cnt[cur], (float)(rend - runstart));
}

// ---------------- head: pooled @ W_out + b_out, layernorm ----------------
__global__ void final_kernel(const float* __restrict__ Wo, const float* __restrict__ bo,
                             const float* __restrict__ gamma, const float* __restrict__ beta,
                             float* __restrict__ out) {
    __shared__ float p[HIDDEN];
    __shared__ float rs[DMODEL];
    __shared__ float rq[DMODEL];
    int b = blockIdx.x, c = threadIdx.x;
    if (c < HIDDEN) {
        float cnt = fmaxf(g_cnt[b], 1.f);
        p[c] = g_summ[b * HIDDEN + c] / cnt;
    }
    __syncthreads();
    float y = bo[c];
#pragma unroll 8
    for (int k = 0; k < HIDDEN; k++) y += p[k] * Wo[k * DMODEL + c];
    rs[c] = y;
    rq[c] = y * y;
    __syncthreads();
    for (int s = DMODEL / 2; s > 0; s >>= 1) {
        if (c < s) { rs[c] += rs[c + s]; rq[c] += rq[c + s]; }
        __syncthreads();
    }
    float mu = rs[0] / (float)DMODEL;
    float var = rq[0] / (float)DMODEL - mu * mu;
    out[b * DMODEL + c] = (y - mu) * rsqrtf(var + EPSV) * gamma[c] + beta[c];
}

// ---------------- launch ----------------
extern "C" void kernel_launch(void* const* d_in, const int* in_sizes, int n_in,
                              void* d_out, int out_size) {
    const float* vertices = (const float*)d_in[0];
    const int*   eidx     = (const int*)d_in[1];
    const int*   batch    = (const int*)d_in[2];
    const float* W_in     = (const float*)d_in[3];
    const float* b_in     = (const float*)d_in[4];
    const float* W1       = (const float*)d_in[5];
    const float* b1       = (const float*)d_in[6];
    const float* W2       = (const float*)d_in[7];
    const float* b2       = (const float*)d_in[8];
    const float* W3       = (const float*)d_in[9];
    const float* b3       = (const float*)d_in[10];
    const float* W_out    = (const float*)d_in[11];
    const float* b_out    = (const float*)d_in[12];
    const float* gamma    = (const float*)d_in[13];
    const float* beta     = (const float*)d_in[14];
    const int* src = eidx;
    const int* dst = eidx + EE;
    float* out = (float*)d_out;

    float *ph, *pA, *pB;
    cudaGetSymbolAddress((void**)&ph, g_h);
    cudaGetSymbolAddress((void**)&pA, g_bufA);
    cudaGetSymbolAddress((void**)&pB, g_bufB);

    size_t smem = (HIDDEN * HIDDEN + 64 * 132) * sizeof(float);  // ~97.6 KB
    cudaFuncSetAttribute(gemm_kernel<false>, cudaFuncAttributeMaxDynamicSharedMemorySize, (int)smem);
    cudaFuncSetAttribute(gemm_kernel<true>,  cudaFuncAttributeMaxDynamicSharedMemorySize, (int)smem);

    int nb256 = (NV + 255) / 256;
    zero_kernel<<<nb256, 256>>>();
    deg_kernel<<<(EE + 255) / 256, 256>>>(dst);
    blocksum_kernel<<<NBLK, 256>>>();
    scanbsum_kernel<<<1, 512>>>();
    scanfinal_kernel<<<NBLK, 256>>>();
    dinv_kernel<<<nb256, 256>>>();
    sort_kernel<<<(EE + 255) / 256, 256>>>(src, dst);
    input_kernel<<<(NV * 32 + 255) / 256, 256>>>(vertices, W_in, b_in);

    int gblocks = (NV + 63) / 64;
    int ablocks = (int)(((long long)NV * 32 + 255) / 256);

    gemm_kernel<false><<<gblocks, 256, smem>>>(pA, W1, ph);
    agg_kernel<<<ablocks, 256>>>(ph, b1, pB);

    gemm_kernel<true><<<gblocks, 256, smem>>>(pB, W2, ph);
    agg_kernel<<<ablocks, 256>>>(ph, b2, pA);

    gemm_kernel<true><<<gblocks, 256, smem>>>(pA, W3, ph);
    agg_kernel<<<ablocks, 256>>>(ph, b3, pB);

    pool_kernel<<<(NV + POOL_ROWS - 1) / POOL_ROWS, HIDDEN>>>(pB, batch);
    final_kernel<<<BB, DMODEL>>>(W_out, b_out, gamma, beta, out);
}

// round 3
// speedup vs baseline: 3.7881x; 1.4152x over previous
#include <cuda_runtime.h>
#include <cuda_bf16.h>
#include <cstdint>

#define NV 100000
#define EE 1600000
#define BB 64
#define HIDDEN 128
#define DMODEL 256
#define EPSV 1e-5f
#define POOL_ROWS 128
#define NBLK ((NV + 255) / 256)   // 391 scan blocks

// ---------------- scratch (static device globals; no allocation) ----------------
__device__ float g_h[NV * HIDDEN];      // pre-aggregation features h = x @ W
__device__ float g_bufA[NV * HIDDEN];   // ping
__device__ float g_bufB[NV * HIDDEN];   // pong
__device__ float g_dinv[NV];            // deg^{-1/2}
__device__ int   g_deg[NV];             // in-degree
__device__ int   g_rowptr[NV + 1];      // CSR offsets (by dst)
__device__ int   g_pos[NV];             // running insert positions for sort
__device__ int   g_bsum[NBLK];          // block partial sums for scan
__device__ int2  g_epack[EE];           // sorted edges: {src, bits(w)}
__device__ float g_summ[BB * HIDDEN];   // pooled sums
__device__ float g_cnt[BB];             // pooled counts

// ---------------- setup kernels ----------------
__global__ void zero_kernel() {
    int i = blockIdx.x * blockDim.x + threadIdx.x;
    if (i < NV) g_deg[i] = 0;
    if (i < BB * HIDDEN) g_summ[i] = 0.f;
    if (i < BB) g_cnt[i] = 0.f;
}

__global__ void deg_kernel(const int* __restrict__ dst) {
    int e = blockIdx.x * blockDim.x + threadIdx.x;
    if (e < EE) atomicAdd(&g_deg[dst[e]], 1);
}

__global__ void dinv_kernel() {
    int i = blockIdx.x * blockDim.x + threadIdx.x;
    if (i < NV) g_dinv[i] = rsqrtf((float)g_deg[i] + 1.f);
}

// --- two-level exclusive scan of g_deg -> g_rowptr / g_pos ---
__global__ void blocksum_kernel() {
    __shared__ int s[256];
    int tid = threadIdx.x;
    int i = blockIdx.x * 256 + tid;
    int v = (i < NV) ? g_deg[i] : 0;
    s[tid] = v;
    __syncthreads();
#pragma unroll
    for (int st = 128; st > 0; st >>= 1) {
        if (tid < st) s[tid] += s[tid + st];
        __syncthreads();
    }
    if (tid == 0) g_bsum[blockIdx.x] = s[0];
}

__global__ void scanbsum_kernel() {  // single block, 512 threads, NBLK <= 512
    __shared__ int s[512];
    int tid = threadIdx.x;
    int v = (tid < NBLK) ? g_bsum[tid] : 0;
    s[tid] = v;
    __syncthreads();
#pragma unroll
    for (int off = 1; off < 512; off <<= 1) {
        int t = (tid >= off) ? s[tid - off] : 0;
        __syncthreads();
        s[tid] += t;
        __syncthreads();
    }
    if (tid < NBLK) g_bsum[tid] = s[tid] - v;  // exclusive
}

__global__ void scanfinal_kernel() {
    __shared__ int s[256];
    int tid = threadIdx.x;
    int i = blockIdx.x * 256 + tid;
    int v = (i < NV) ? g_deg[i] : 0;
    s[tid] = v;
    __syncthreads();
#pragma unroll
    for (int off = 1; off < 256; off <<= 1) {
        int t = (tid >= off) ? s[tid - off] : 0;
        __syncthreads();
        s[tid] += t;
        __syncthreads();
    }
    int ex = s[tid] - v + g_bsum[blockIdx.x];
    if (i < NV) { g_rowptr[i] = ex; g_pos[i] = ex; }
    if (i == NV - 1) g_rowptr[NV] = ex + v;
}

// counting-sort edges by dst; pack {src, w} per edge
__global__ void sort_kernel(const int* __restrict__ src, const int* __restrict__ dst) {
    int e = blockIdx.x * blockDim.x + threadIdx.x;
    if (e >= EE) return;
    int s = src[e], d = dst[e];
    int p = atomicAdd(&g_pos[d], 1);
    float w = g_dinv[s] * g_dinv[d];
    g_epack[p] = make_int2(s, __float_as_int(w));
}

// ---------------- input projection: x0 = vertices @ W_in + b_in ----------------
__global__ void input_kernel(const float* __restrict__ v,
                             const float* __restrict__ Wi,
                             const float* __restrict__ bi) {
    __shared__ float sw[3 * HIDDEN + HIDDEN];
    for (int i = threadIdx.x; i < 4 * HIDDEN; i += 256)
        sw[i] = (i < 3 * HIDDEN) ? Wi[i] : bi[i - 3 * HIDDEN];
    __syncthreads();
    int t = blockIdx.x * 256 + threadIdx.x;
    int row = t >> 5, q = t & 31;
    if (row >= NV) return;
    float v0 = v[row * 3 + 0], v1 = v[row * 3 + 1], v2 = v[row * 3 + 2];
    int c = q * 4;
    float4 o;
    float* po = &o.x;
#pragma unroll
    for (int j = 0; j < 4; j++) {
        int cc = c + j;
        po[j] = sw[3 * HIDDEN + cc] + v0 * sw[cc] + v1 * sw[HIDDEN + cc] + v2 * sw[2 * HIDDEN + cc];
    }
    *((float4*)g_bufA + row * 32 + q) = o;
}

// ---------------- tensor-core GEMM: H = act(X) @ W (bf16x3 split) ----------------
// Block: 256 threads, output tile 128x128. Warp (8 of them, 4x2): 32 rows x 64 cols.
// smem: Xh/Xl row-major [r][k], Wh/Wl transposed [n][k], stride 136 bf16.

__device__ __forceinline__ void mma_bf16(float* c, const uint32_t* a,
                                         uint32_t b0, uint32_t b1) {
    asm volatile(
        "mma.sync.aligned.m16n8k16.row.col.f32.bf16.bf16.f32 "
        "{%0,%1,%2,%3}, {%4,%5,%6,%7}, {%8,%9}, {%0,%1,%2,%3};\n"
        : "+f"(c[0]), "+f"(c[1]), "+f"(c[2]), "+f"(c[3])
        : "r"(a[0]), "r"(a[1]), "r"(a[2]), "r"(a[3]), "r"(b0), "r"(b1));
}

#define BST 136          // smem row stride in bf16 elements
#define BSTW 68          // same, in 32-bit words
#define XTILE (128 * BST)

template <bool RELU>
__global__ void gemm_tc_kernel(const float* __restrict__ X,
                               const float* __restrict__ W,
                               float* __restrict__ H) {
    extern __shared__ __nv_bfloat16 sb[];
    __nv_bfloat16* Xh = sb;
    __nv_bfloat16* Xl = sb + XTILE;
    __nv_bfloat16* Wh = sb + 2 * XTILE;
    __nv_bfloat16* Wl = sb + 3 * XTILE;
    int t = threadIdx.x;
    int row0 = blockIdx.x * 128;

    // --- load W [k][n] row-major global, store transposed [n][k] split hi/lo ---
#pragma unroll
    for (int i = 0; i < 64; i++) {
        int idx = i * 256 + t;          // 0..16383
        int k = idx >> 7, n = idx & 127;
        float w = W[idx];
        __nv_bfloat16 wh = __float2bfloat16_rn(w);
        float rem = w - __bfloat162float(wh);
        Wh[n * BST + k] = wh;
        Wl[n * BST + k] = __float2bfloat16_rn(rem);
    }
    // --- load X tile [128][128] fp32, relu, split hi/lo, row-major ---
#pragma unroll
    for (int i = 0; i < 16; i++) {
        int idx = i * 256 + t;          // 0..4095 float4 slots
        int r = idx >> 5, q = idx & 31;
        int gr = row0 + r;
        float4 v = make_float4(0.f, 0.f, 0.f, 0.f);
        if (gr < NV) {
            v = *((const float4*)X + gr * 32 + q);
            if (RELU) {
                v.x = fmaxf(v.x, 0.f); v.y = fmaxf(v.y, 0.f);
                v.z = fmaxf(v.z, 0.f); v.w = fmaxf(v.w, 0.f);
            }
        }
        __nv_bfloat162 h0 = __floats2bfloat162_rn(v.x, v.y);
        __nv_bfloat162 h1 = __floats2bfloat162_rn(v.z, v.w);
        float2 hf0 = __bfloat1622float2(h0);
        float2 hf1 = __bfloat1622float2(h1);
        __nv_bfloat162 l0 = __floats2bfloat162_rn(v.x - hf0.x, v.y - hf0.y);
        __nv_bfloat162 l1 = __floats2bfloat162_rn(v.z - hf1.x, v.w - hf1.y);
        int base = r * BST + q * 4;     // even -> 32-bit aligned
        *(__nv_bfloat162*)(Xh + base) = h0;
        *(__nv_bfloat162*)(Xh + base + 2) = h1;
        *(__nv_bfloat162*)(Xl + base) = l0;
        *(__nv_bfloat162*)(Xl + base + 2) = l1;
    }
    __syncthreads();

    int w = t >> 5, lane = t & 31;
    int wr = w >> 1, wc = w & 1;        // warp row (0..3) / col (0..1)
    int g = lane >> 2, q4 = lane & 3;

    float acc[2][8][4];
#pragma unroll
    for (int mt = 0; mt < 2; mt++)
#pragma unroll
        for (int nt = 0; nt < 8; nt++)
#pragma unroll
            for (int j = 0; j < 4; j++) acc[mt][nt][j] = 0.f;

    const uint32_t* pXh = (const uint32_t*)Xh;
    const uint32_t* pXl = (const uint32_t*)Xl;
    const uint32_t* pWh = (const uint32_t*)Wh;
    const uint32_t* pWl = (const uint32_t*)Wl;

#pragma unroll
    for (int ks = 0; ks < 8; ks++) {
        int kw = ks * 8 + q4;           // word offset in row
        uint32_t ah[2][4], al[2][4];
#pragma unroll
        for (int mt = 0; mt < 2; mt++) {
            int r = wr * 32 + mt * 16 + g;
            ah[mt][0] = pXh[r * BSTW + kw];
            ah[mt][1] = pXh[(r + 8) * BSTW + kw];
            ah[mt][2] = pXh[r * BSTW + kw + 4];
            ah[mt][3] = pXh[(r + 8) * BSTW + kw + 4];
            al[mt][0] = pXl[r * BSTW + kw];
            al[mt][1] = pXl[(r + 8) * BSTW + kw];
            al[mt][2] = pXl[r * BSTW + kw + 4];
            al[mt][3] = pXl[(r + 8) * BSTW + kw + 4];
        }
#pragma unroll
        for (int nt = 0; nt < 8; nt++) {
            int n = wc * 64 + nt * 8 + g;
            uint32_t bh0 = pWh[n * BSTW + kw];
            uint32_t bh1 = pWh[n * BSTW + kw + 4];
            uint32_t bl0 = pWl[n * BSTW + kw];
            uint32_t bl1 = pWl[n * BSTW + kw + 4];
#pragma unroll
            for (int mt = 0; mt < 2; mt++) {
                mma_bf16(acc[mt][nt], ah[mt], bh0, bh1);
                mma_bf16(acc[mt][nt], ah[mt], bl0, bl1);
                mma_bf16(acc[mt][nt], al[mt], bh0, bh1);
            }
        }
    }

    // --- epilogue: c0,c1 -> (row g), c2,c3 -> (row g+8), col pair q4*2 ---
#pragma unroll
    for (int mt = 0; mt < 2; mt++) {
#pragma unroll
        for (int nt = 0; nt < 8; nt++) {
            int col = wc * 64 + nt * 8 + q4 * 2;
            int r = row0 + wr * 32 + mt * 16 + g;
            if (r < NV)
                *(float2*)(H + r * HIDDEN + col) =
                    make_float2(acc[mt][nt][0], acc[mt][nt][1]);
            int r2 = r + 8;
            if (r2 < NV)
                *(float2*)(H + r2 * HIDDEN + col) =
                    make_float2(acc[mt][nt][2], acc[mt][nt][3]);
        }
    }
}

// ---------------- aggregation: one warp per dst row, zero atomics ----------------
// OUT[r] = H[r]*dinv[r]^2 + bias + sum_{e in CSR[r]} w_e * H[src_e]
__global__ void agg_kernel(const float* __restrict__ H,
                           const float* __restrict__ bias,
                           float* __restrict__ OUT) {
    int gw = (blockIdx.x * blockDim.x + threadIdx.x) >> 5;
    int lane = threadIdx.x & 31;
    if (gw >= NV) return;
    int beg = g_rowptr[gw], end = g_rowptr[gw + 1];
    float dd = g_dinv[gw];
    dd *= dd;
    float4 h = *((const float4*)H + gw * 32 + lane);
    float4 b = *((const float4*)bias + lane);
    float4 acc = make_float4(h.x * dd + b.x, h.y * dd + b.y,
                             h.z * dd + b.z, h.w * dd + b.w);

    int e = beg;
    for (; e + 1 < end; e += 2) {   // 2-way unroll for MLP
        int2 p0 = g_epack[e];
        int2 p1 = g_epack[e + 1];
        float w0 = __int_as_float(p0.y);
        float w1 = __int_as_float(p1.y);
        float4 v0 = *((const float4*)H + p0.x * 32 + lane);
        float4 v1 = *((const float4*)H + p1.x * 32 + lane);
        acc.x += w0 * v0.x + w1 * v1.x;
        acc.y += w0 * v0.y + w1 * v1.y;
        acc.z += w0 * v0.z + w1 * v1.z;
        acc.w += w0 * v0.w + w1 * v1.w;
    }
    if (e < end) {
        int2 p = g_epack[e];
        float w = __int_as_float(p.y);
        float4 v = *((const float4*)H + p.x * 32 + lane);
        acc.x += w * v.x; acc.y += w * v.y;
        acc.z += w * v.z; acc.w += w * v.w;
    }
    *((float4*)OUT + gw * 32 + lane) = acc;
}

// ---------------- pooling over sorted batch ----------------
__global__ void pool_kernel(const float* __restrict__ X, const int* __restrict__ batch) {
    int c = threadIdx.x;
    int row0 = blockIdx.x * POOL_ROWS;
    if (row0 >= NV) return;
    int rend = min(row0 + POOL_ROWS, NV);
    float acc = 0.f;
    int cur = batch[row0];
    int runstart = row0;
    for (int r = row0; r < rend; r++) {
        int b = batch[r];
        if (b != cur) {
            atomicAdd(&g_summ[cur * HIDDEN + c], acc);
            if (c == 0) atomicAdd(&g_cnt[cur], (float)(r - runstart));
            acc = 0.f; cur = b; runstart = r;
        }
        acc += fmaxf(X[(long long)r * HIDDEN + c], 0.f);
    }
    atomicAdd(&g_summ[cur * HIDDEN + c], acc);
    if (c == 0) atomicAdd(&g_cnt[cur], (float)(rend - runstart));
}

// ---------------- head: pooled @ W_out + b_out, layernorm ----------------
__global__ void final_kernel(const float* __restrict__ Wo, const float* __restrict__ bo,
                             const float* __restrict__ gamma, const float* __restrict__ beta,
                             float* __restrict__ out) {
    __shared__ float p[HIDDEN];
    __shared__ float rs[DMODEL];
    __shared__ float rq[DMODEL];
    int b = blockIdx.x, c = threadIdx.x;
    if (c < HIDDEN) {
        float cnt = fmaxf(g_cnt[b], 1.f);
        p[c] = g_summ[b * HIDDEN + c] / cnt;
    }
    __syncthreads();
    float y = bo[c];
#pragma unroll 8
    for (int k = 0; k < HIDDEN; k++) y += p[k] * Wo[k * DMODEL + c];
    rs[c] = y;
    rq[c] = y * y;
    __syncthreads();
    for (int s = DMODEL / 2; s > 0; s >>= 1) {
        if (c < s) { rs[c] += rs[c + s]; rq[c] += rq[c + s]; }
        __syncthreads();
    }
    float mu = rs[0] / (float)DMODEL;
    float var = rq[0] / (float)DMODEL - mu * mu;
    out[b * DMODEL + c] = (y - mu) * rsqrtf(var + EPSV) * gamma[c] + beta[c];
}

// ---------------- launch ----------------
extern "C" void kernel_launch(void* const* d_in, const int* in_sizes, int n_in,
                              void* d_out, int out_size) {
    const float* vertices = (const float*)d_in[0];
    const int*   eidx     = (const int*)d_in[1];
    const int*   batch    = (const int*)d_in[2];
    const float* W_in     = (const float*)d_in[3];
    const float* b_in     = (const float*)d_in[4];
    const float* W1       = (const float*)d_in[5];
    const float* b1       = (const float*)d_in[6];
    const float* W2       = (const float*)d_in[7];
    const float* b2       = (const float*)d_in[8];
    const float* W3       = (const float*)d_in[9];
    const float* b3       = (const float*)d_in[10];
    const float* W_out    = (const float*)d_in[11];
    const float* b_out    = (const float*)d_in[12];
    const float* gamma    = (const float*)d_in[13];
    const float* beta     = (const float*)d_in[14];
    const int* src = eidx;
    const int* dst = eidx + EE;
    float* out = (float*)d_out;

    float *ph, *pA, *pB;
    cudaGetSymbolAddress((void**)&ph, g_h);
    cudaGetSymbolAddress((void**)&pA, g_bufA);
    cudaGetSymbolAddress((void**)&pB, g_bufB);

    size_t smem = 4 * XTILE * sizeof(__nv_bfloat16);  // 139,264 B
    cudaFuncSetAttribute(gemm_tc_kernel<false>, cudaFuncAttributeMaxDynamicSharedMemorySize, (int)smem);
    cudaFuncSetAttribute(gemm_tc_kernel<true>,  cudaFuncAttributeMaxDynamicSharedMemorySize, (int)smem);

    int nb256 = (NV + 255) / 256;
    zero_kernel<<<nb256, 256>>>();
    deg_kernel<<<(EE + 255) / 256, 256>>>(dst);
    blocksum_kernel<<<NBLK, 256>>>();
    scanbsum_kernel<<<1, 512>>>();
    scanfinal_kernel<<<NBLK, 256>>>();
    dinv_kernel<<<nb256, 256>>>();
    sort_kernel<<<(EE + 255) / 256, 256>>>(src, dst);
    input_kernel<<<(NV * 32 + 255) / 256, 256>>>(vertices, W_in, b_in);

    int gblocks = (NV + 127) / 128;
    int ablocks = (int)(((long long)NV * 32 + 255) / 256);

    gemm_tc_kernel<false><<<gblocks, 256, smem>>>(pA, W1, ph);
    agg_kernel<<<ablocks, 256>>>(ph, b1, pB);

    gemm_tc_kernel<true><<<gblocks, 256, smem>>>(pB, W2, ph);
    agg_kernel<<<ablocks, 256>>>(ph, b2, pA);

    gemm_tc_kernel<true><<<gblocks, 256, smem>>>(pA, W3, ph);
    agg_kernel<<<ablocks, 256>>>(ph, b3, pB);

    pool_kernel<<<(NV + POOL_ROWS - 1) / POOL_ROWS, HIDDEN>>>(pB, batch);
    final_kernel<<<BB, DMODEL>>>(W_out, b_out, gamma, beta, out);
}

// round 6
// speedup vs baseline: 4.5059x; 1.1895x over previous
#include <cuda_runtime.h>
#include <cuda_bf16.h>
#include <cuda_fp16.h>
#include <cstdint>

#define NV 100000
#define EE 1600000
#define BB 64
#define HIDDEN 128
#define DMODEL 256
#define EPSV 1e-5f
#define POOL_ROWS 128
#define NBLK ((NV + 255) / 256)   // 391 scan blocks

// ---------------- scratch (static device globals; no allocation) ----------------
__device__ __half g_h16[NV * HIDDEN];   // pre-aggregation features (fp16)
__device__ float g_bufA[NV * HIDDEN];   // ping
__device__ float g_bufB[NV * HIDDEN];   // pong
__device__ float g_dinv[NV];            // deg^{-1/2}
__device__ int   g_deg[NV];             // in-degree
__device__ int   g_rowptr[NV + 1];      // CSR offsets (by dst)
__device__ int   g_pos[NV];             // running insert positions for sort
__device__ int   g_bsum[NBLK];          // block partial sums for scan
__device__ int2  g_epack[EE];           // sorted edges: {src, bits(w)}
__device__ float g_summ[BB * HIDDEN];   // pooled sums
__device__ float g_cnt[BB];             // pooled counts

// ---------------- setup kernels ----------------
__global__ void zero_kernel() {
    int i = blockIdx.x * blockDim.x + threadIdx.x;
    if (i < NV) g_deg[i] = 0;
    if (i < BB * HIDDEN) g_summ[i] = 0.f;
    if (i < BB) g_cnt[i] = 0.f;
}

__global__ void deg_kernel(const int* __restrict__ dst) {
    int e = blockIdx.x * blockDim.x + threadIdx.x;
    if (e < EE) atomicAdd(&g_deg[dst[e]], 1);
}

// --- two-level exclusive scan of g_deg -> g_rowptr / g_pos (+ dinv fused) ---
__global__ void blocksum_kernel() {
    __shared__ int s[256];
    int tid = threadIdx.x;
    int i = blockIdx.x * 256 + tid;
    int v = (i < NV) ? g_deg[i] : 0;
    s[tid] = v;
    __syncthreads();
#pragma unroll
    for (int st = 128; st > 0; st >>= 1) {
        if (tid < st) s[tid] += s[tid + st];
        __syncthreads();
    }
    if (tid == 0) g_bsum[blockIdx.x] = s[0];
}

__global__ void scanbsum_kernel() {  // single block, 512 threads, NBLK <= 512
    __shared__ int s[512];
    int tid = threadIdx.x;
    int v = (tid < NBLK) ? g_bsum[tid] : 0;
    s[tid] = v;
    __syncthreads();
#pragma unroll
    for (int off = 1; off < 512; off <<= 1) {
        int t = (tid >= off) ? s[tid - off] : 0;
        __syncthreads();
        s[tid] += t;
        __syncthreads();
    }
    if (tid < NBLK) g_bsum[tid] = s[tid] - v;  // exclusive
}

__global__ void scanfinal_kernel() {
    __shared__ int s[256];
    int tid = threadIdx.x;
    int i = blockIdx.x * 256 + tid;
    int v = (i < NV) ? g_deg[i] : 0;
    s[tid] = v;
    __syncthreads();
#pragma unroll
    for (int off = 1; off < 256; off <<= 1) {
        int t = (tid >= off) ? s[tid - off] : 0;
        __syncthreads();
        s[tid] += t;
        __syncthreads();
    }
    int ex = s[tid] - v + g_bsum[blockIdx.x];
    if (i < NV) {
        g_rowptr[i] = ex;
        g_pos[i] = ex;
        g_dinv[i] = rsqrtf((float)v + 1.f);
    }
    if (i == NV - 1) g_rowptr[NV] = ex + v;
}

// counting-sort edges by dst; pack {src, w} per edge
__global__ void sort_kernel(const int* __restrict__ src, const int* __restrict__ dst) {
    int e = blockIdx.x * blockDim.x + threadIdx.x;
    if (e >= EE) return;
    int s = src[e], d = dst[e];
    int p = atomicAdd(&g_pos[d], 1);
    float w = g_dinv[s] * g_dinv[d];
    g_epack[p] = make_int2(s, __float_as_int(w));
}

// ---------------- input projection: x0 = vertices @ W_in + b_in ----------------
__global__ void input_kernel(const float* __restrict__ v,
                             const float* __restrict__ Wi,
                             const float* __restrict__ bi) {
    __shared__ float sw[3 * HIDDEN + HIDDEN];
    for (int i = threadIdx.x; i < 4 * HIDDEN; i += 256)
        sw[i] = (i < 3 * HIDDEN) ? Wi[i] : bi[i - 3 * HIDDEN];
    __syncthreads();
    int t = blockIdx.x * 256 + threadIdx.x;
    int row = t >> 5, q = t & 31;
    if (row >= NV) return;
    float v0 = v[row * 3 + 0], v1 = v[row * 3 + 1], v2 = v[row * 3 + 2];
    int c = q * 4;
    float4 o;
    float* po = &o.x;
#pragma unroll
    for (int j = 0; j < 4; j++) {
        int cc = c + j;
        po[j] = sw[3 * HIDDEN + cc] + v0 * sw[cc] + v1 * sw[HIDDEN + cc] + v2 * sw[2 * HIDDEN + cc];
    }
    *((float4*)g_bufA + row * 32 + q) = o;
}

// ---------------- tensor-core GEMM: H16 = act(X) @ W (bf16x3 split) ----------------
__device__ __forceinline__ void mma_bf16(float* c, const uint32_t* a,
                                         uint32_t b0, uint32_t b1) {
    asm volatile(
        "mma.sync.aligned.m16n8k16.row.col.f32.bf16.bf16.f32 "
        "{%0,%1,%2,%3}, {%4,%5,%6,%7}, {%8,%9}, {%0,%1,%2,%3};\n"
        : "+f"(c[0]), "+f"(c[1]), "+f"(c[2]), "+f"(c[3])
        : "r"(a[0]), "r"(a[1]), "r"(a[2]), "r"(a[3]), "r"(b0), "r"(b1));
}

#define BST 136          // smem row stride in bf16 elements
#define BSTW 68          // same, in 32-bit words
#define XTILE (128 * BST)

template <bool RELU>
__global__ void gemm_tc_kernel(const float* __restrict__ X,
                               const float* __restrict__ W,
                               __half* __restrict__ H) {
    extern __shared__ __nv_bfloat16 sb[];
    __nv_bfloat16* Xh = sb;
    __nv_bfloat16* Xl = sb + XTILE;
    __nv_bfloat16* Wh = sb + 2 * XTILE;
    __nv_bfloat16* Wl = sb + 3 * XTILE;
    int t = threadIdx.x;
    int row0 = blockIdx.x * 128;

    // W [k][n] global -> transposed [n][k] split hi/lo in smem
#pragma unroll
    for (int i = 0; i < 64; i++) {
        int idx = i * 256 + t;
        int k = idx >> 7, n = idx & 127;
        float w = W[idx];
        __nv_bfloat16 wh = __float2bfloat16_rn(w);
        float rem = w - __bfloat162float(wh);
        Wh[n * BST + k] = wh;
        Wl[n * BST + k] = __float2bfloat16_rn(rem);
    }
    // X tile [128][128] fp32 -> relu -> split hi/lo row-major
#pragma unroll
    for (int i = 0; i < 16; i++) {
        int idx = i * 256 + t;
        int r = idx >> 5, q = idx & 31;
        int gr = row0 + r;
        float4 v = make_float4(0.f, 0.f, 0.f, 0.f);
        if (gr < NV) {
            v = *((const float4*)X + gr * 32 + q);
            if (RELU) {
                v.x = fmaxf(v.x, 0.f); v.y = fmaxf(v.y, 0.f);
                v.z = fmaxf(v.z, 0.f); v.w = fmaxf(v.w, 0.f);
            }
        }
        __nv_bfloat162 h0 = __floats2bfloat162_rn(v.x, v.y);
        __nv_bfloat162 h1 = __floats2bfloat162_rn(v.z, v.w);
        float2 hf0 = __bfloat1622float2(h0);
        float2 hf1 = __bfloat1622float2(h1);
        __nv_bfloat162 l0 = __floats2bfloat162_rn(v.x - hf0.x, v.y - hf0.y);
        __nv_bfloat162 l1 = __floats2bfloat162_rn(v.z - hf1.x, v.w - hf1.y);
        int base = r * BST + q * 4;
        *(__nv_bfloat162*)(Xh + base) = h0;
        *(__nv_bfloat162*)(Xh + base + 2) = h1;
        *(__nv_bfloat162*)(Xl + base) = l0;
        *(__nv_bfloat162*)(Xl + base + 2) = l1;
    }
    __syncthreads();

    int w = t >> 5, lane = t & 31;
    int wr = w >> 1, wc = w & 1;
    int g = lane >> 2, q4 = lane & 3;

    float acc[2][8][4];
#pragma unroll
    for (int mt = 0; mt < 2; mt++)
#pragma unroll
        for (int nt = 0; nt < 8; nt++)
#pragma unroll
            for (int j = 0; j < 4; j++) acc[mt][nt][j] = 0.f;

    const uint32_t* pXh = (const uint32_t*)Xh;
    const uint32_t* pXl = (const uint32_t*)Xl;
    const uint32_t* pWh = (const uint32_t*)Wh;
    const uint32_t* pWl = (const uint32_t*)Wl;

#pragma unroll
    for (int ks = 0; ks < 8; ks++) {
        int kw = ks * 8 + q4;
        uint32_t ah[2][4], al[2][4];
#pragma unroll
        for (int mt = 0; mt < 2; mt++) {
            int r = wr * 32 + mt * 16 + g;
            ah[mt][0] = pXh[r * BSTW + kw];
            ah[mt][1] = pXh[(r + 8) * BSTW + kw];
            ah[mt][2] = pXh[r * BSTW + kw + 4];
            ah[mt][3] = pXh[(r + 8) * BSTW + kw + 4];
            al[mt][0] = pXl[r * BSTW + kw];
            al[mt][1] = pXl[(r + 8) * BSTW + kw];
            al[mt][2] = pXl[r * BSTW + kw + 4];
            al[mt][3] = pXl[(r + 8) * BSTW + kw + 4];
        }
#pragma unroll
        for (int nt = 0; nt < 8; nt++) {
            int n = wc * 64 + nt * 8 + g;
            uint32_t bh0 = pWh[n * BSTW + kw];
            uint32_t bh1 = pWh[n * BSTW + kw + 4];
            uint32_t bl0 = pWl[n * BSTW + kw];
            uint32_t bl1 = pWl[n * BSTW + kw + 4];
#pragma unroll
            for (int mt = 0; mt < 2; mt++) {
                mma_bf16(acc[mt][nt], ah[mt], bh0, bh1);
                mma_bf16(acc[mt][nt], ah[mt], bl0, bl1);
                mma_bf16(acc[mt][nt], al[mt], bh0, bh1);
            }
        }
    }

    // epilogue: fp32 acc -> half2 stores
#pragma unroll
    for (int mt = 0; mt < 2; mt++) {
#pragma unroll
        for (int nt = 0; nt < 8; nt++) {
            int col = wc * 64 + nt * 8 + q4 * 2;
            int r = row0 + wr * 32 + mt * 16 + g;
            if (r < NV)
                *(__half2*)(H + r * HIDDEN + col) =
                    __floats2half2_rn(acc[mt][nt][0], acc[mt][nt][1]);
            int r2 = r + 8;
            if (r2 < NV)
                *(__half2*)(H + r2 * HIDDEN + col) =
                    __floats2half2_rn(acc[mt][nt][2], acc[mt][nt][3]);
        }
    }
}

// ---------------- aggregation: one warp per dst row, fp16 gather ----------------
__device__ __forceinline__ float4 h4_to_f4(uint2 u) {
    float2 f0 = __half22float2(*(__half2*)&u.x);
    float2 f1 = __half22float2(*(__half2*)&u.y);
    return make_float4(f0.x, f0.y, f1.x, f1.y);
}

__global__ void agg_kernel(const __half* __restrict__ H,
                           const float* __restrict__ bias,
                           float* __restrict__ OUT) {
    int gw = (blockIdx.x * blockDim.x + threadIdx.x) >> 5;
    int lane = threadIdx.x & 31;
    if (gw >= NV) return;
    int beg = g_rowptr[gw], end = g_rowptr[gw + 1];
    float dd = g_dinv[gw];
    dd *= dd;
    const uint2* Hp = (const uint2*)H;   // 8B = 4 halfs per lane
    float4 h = h4_to_f4(Hp[gw * 32 + lane]);
    float4 b = *((const float4*)bias + lane);
    float4 acc = make_float4(h.x * dd + b.x, h.y * dd + b.y,
                             h.z * dd + b.z, h.w * dd + b.w);

    int e = beg;
    for (; e + 3 < end; e += 4) {
        int2 p0 = g_epack[e];
        int2 p1 = g_epack[e + 1];
        int2 p2 = g_epack[e + 2];
        int2 p3 = g_epack[e + 3];
        float4 v0 = h4_to_f4(Hp[p0.x * 32 + lane]);
        float4 v1 = h4_to_f4(Hp[p1.x * 32 + lane]);
        float4 v2 = h4_to_f4(Hp[p2.x * 32 + lane]);
        float4 v3 = h4_to_f4(Hp[p3.x * 32 + lane]);
        float w0 = __int_as_float(p0.y);
        float w1 = __int_as_float(p1.y);
        float w2 = __int_as_float(p2.y);
        float w3 = __int_as_float(p3.y);
        acc.x += w0 * v0.x + w1 * v1.x + w2 * v2.x + w3 * v3.x;
        acc.y += w0 * v0.y + w1 * v1.y + w2 * v2.y + w3 * v3.y;
        acc.z += w0 * v0.z + w1 * v1.z + w2 * v2.z + w3 * v3.z;
        acc.w += w0 * v0.w + w1 * v1.w + w2 * v2.w + w3 * v3.w;
    }
    for (; e < end; e++) {
        int2 p = g_epack[e];
        float w = __int_as_float(p.y);
        float4 v = h4_to_f4(Hp[p.x * 32 + lane]);
        acc.x += w * v.x; acc.y += w * v.y;
        acc.z += w * v.z; acc.w += w * v.w;
    }
    *((float4*)OUT + gw * 32 + lane) = acc;
}

// ---------------- pooling over sorted batch ----------------
__global__ void pool_kernel(const float* __restrict__ X, const int* __restrict__ batch) {
    int c = threadIdx.x;
    int row0 = blockIdx.x * POOL_ROWS;
    if (row0 >= NV) return;
    int rend = min(row0 + POOL_ROWS, NV);
    float acc = 0.f;
    int cur = batch[row0];
    int runstart = row0;
    for (int r = row0; r < rend; r++) {
        int b = batch[r];
        if (b != cur) {
            atomicAdd(&g_summ[cur * HIDDEN + c], acc);
            if (c == 0) atomicAdd(&g_cnt[cur], (float)(r - runstart));
            acc = 0.f; cur = b; runstart = r;
        }
        acc += fmaxf(X[(long long)r * HIDDEN + c], 0.f);
    }
    atomicAdd(&g_summ[cur * HIDDEN + c], acc);
    if (c == 0) atomicAdd(&g_cnt[cur], (float)(rend - runstart));
}

// ---------------- head: pooled @ W_out + b_out, layernorm ----------------
__global__ void final_kernel(const float* __restrict__ Wo, const float* __restrict__ bo,
                             const float* __restrict__ gamma, const float* __restrict__ beta,
                             float* __restrict__ out) {
    __shared__ float p[HIDDEN];
    __shared__ float rs[DMODEL];
    __shared__ float rq[DMODEL];
    int b = blockIdx.x, c = threadIdx.x;
    if (c < HIDDEN) {
        float cnt = fmaxf(g_cnt[b], 1.f);
        p[c] = g_summ[b * HIDDEN + c] / cnt;
    }
    __syncthreads();
    float y = bo[c];
#pragma unroll 8
    for (int k = 0; k < HIDDEN; k++) y += p[k] * Wo[k * DMODEL + c];
    rs[c] = y;
    rq[c] = y * y;
    __syncthreads();
    for (int s = DMODEL / 2; s > 0; s >>= 1) {
        if (c < s) { rs[c] += rs[c + s]; rq[c] += rq[c + s]; }
        __syncthreads();
    }
    float mu = rs[0] / (float)DMODEL;
    float var = rq[0] / (float)DMODEL - mu * mu;
    out[b * DMODEL + c] = (y - mu) * rsqrtf(var + EPSV) * gamma[c] + beta[c];
}

// ---------------- launch ----------------
extern "C" void kernel_launch(void* const* d_in, const int* in_sizes, int n_in,
                              void* d_out, int out_size) {
    const float* vertices = (const float*)d_in[0];
    const int*   eidx     = (const int*)d_in[1];
    const int*   batch    = (const int*)d_in[2];
    const float* W_in     = (const float*)d_in[3];
    const float* b_in     = (const float*)d_in[4];
    const float* W1       = (const float*)d_in[5];
    const float* b1       = (const float*)d_in[6];
    const float* W2       = (const float*)d_in[7];
    const float* b2       = (const float*)d_in[8];
    const float* W3       = (const float*)d_in[9];
    const float* b3       = (const float*)d_in[10];
    const float* W_out    = (const float*)d_in[11];
    const float* b_out    = (const float*)d_in[12];
    const float* gamma    = (const float*)d_in[13];
    const float* beta     = (const float*)d_in[14];
    const int* src = eidx;
    const int* dst = eidx + EE;
    float* out = (float*)d_out;

    __half* ph;
    float *pA, *pB;
    cudaGetSymbolAddress((void**)&ph, g_h16);
    cudaGetSymbolAddress((void**)&pA, g_bufA);
    cudaGetSymbolAddress((void**)&pB, g_bufB);

    size_t smem = 4 * XTILE * sizeof(__nv_bfloat16);  // 139,264 B
    cudaFuncSetAttribute(gemm_tc_kernel<false>, cudaFuncAttributeMaxDynamicSharedMemorySize, (int)smem);
    cudaFuncSetAttribute(gemm_tc_kernel<true>,  cudaFuncAttributeMaxDynamicSharedMemorySize, (int)smem);

    int nb256 = (NV + 255) / 256;
    zero_kernel<<<nb256, 256>>>();
    deg_kernel<<<(EE + 255) / 256, 256>>>(dst);
    blocksum_kernel<<<NBLK, 256>>>();
    scanbsum_kernel<<<1, 512>>>();
    scanfinal_kernel<<<NBLK, 256>>>();
    sort_kernel<<<(EE + 255) / 256, 256>>>(src, dst);
    input_kernel<<<(NV * 32 + 255) / 256, 256>>>(vertices, W_in, b_in);

    int gblocks = (NV + 127) / 128;
    int ablocks = (int)(((long long)NV * 32 + 255) / 256);

    gemm_tc_kernel<false><<<gblocks, 256, smem>>>(pA, W1, ph);
    agg_kernel<<<ablocks, 256>>>(ph, b1, pB);

    gemm_tc_kernel<true><<<gblocks, 256, smem>>>(pB, W2, ph);
    agg_kernel<<<ablocks, 256>>>(ph, b2, pA);

    gemm_tc_kernel<true><<<gblocks, 256, smem>>>(pA, W3, ph);
    agg_kernel<<<ablocks, 256>>>(ph, b3, pB);

    pool_kernel<<<(NV + POOL_ROWS - 1) / POOL_ROWS, HIDDEN>>>(pB, batch);
    final_kernel<<<BB, DMODEL>>>(W_out, b_out, gamma, beta, out);
}

// round 7
// speedup vs baseline: 4.9304x; 1.0942x over previous
#include <cuda_runtime.h>
#include <cuda_bf16.h>
#include <cuda_fp16.h>
#include <cstdint>

#define NV 100000
#define EE 1600000
#define BB 64
#define HIDDEN 128
#define DMODEL 256
#define EPSV 1e-5f
#define POOL_ROWS 128
#define NBLK ((NV + 255) / 256)   // 391 scan blocks

// ---------------- scratch (static device globals; no allocation) ----------------
__device__ __half g_h16[NV * HIDDEN];   // pre-aggregation features (fp16)
__device__ __half g_x16a[NV * HIDDEN];  // activation ping (fp16)
__device__ __half g_x16b[NV * HIDDEN];  // activation pong (fp16)
__device__ float g_dinv[NV];            // deg^{-1/2}
__device__ int   g_deg[NV];             // in-degree
__device__ int   g_rowptr[NV + 1];      // CSR offsets (by dst)
__device__ int   g_pos[NV];             // running insert positions for sort
__device__ int   g_bsum[NBLK];          // block partial sums for scan
__device__ int2  g_epack[EE];           // sorted edges: {src, bits(w)}
__device__ float g_summ[BB * HIDDEN];   // pooled sums
__device__ float g_cnt[BB];             // pooled counts

// ---------------- setup kernels ----------------
__global__ void zero_kernel() {
    int i = blockIdx.x * blockDim.x + threadIdx.x;
    if (i < NV) g_deg[i] = 0;
    if (i < BB * HIDDEN) g_summ[i] = 0.f;
    if (i < BB) g_cnt[i] = 0.f;
}

__global__ void deg_kernel(const int* __restrict__ dst) {
    int e = blockIdx.x * blockDim.x + threadIdx.x;
    if (e < EE) atomicAdd(&g_deg[dst[e]], 1);
}

// --- two-level exclusive scan of g_deg -> g_rowptr / g_pos (+ dinv fused) ---
__global__ void blocksum_kernel() {
    __shared__ int s[256];
    int tid = threadIdx.x;
    int i = blockIdx.x * 256 + tid;
    int v = (i < NV) ? g_deg[i] : 0;
    s[tid] = v;
    __syncthreads();
#pragma unroll
    for (int st = 128; st > 0; st >>= 1) {
        if (tid < st) s[tid] += s[tid + st];
        __syncthreads();
    }
    if (tid == 0) g_bsum[blockIdx.x] = s[0];
}

__global__ void scanbsum_kernel() {  // single block, 512 threads, NBLK <= 512
    __shared__ int s[512];
    int tid = threadIdx.x;
    int v = (tid < NBLK) ? g_bsum[tid] : 0;
    s[tid] = v;
    __syncthreads();
#pragma unroll
    for (int off = 1; off < 512; off <<= 1) {
        int t = (tid >= off) ? s[tid - off] : 0;
        __syncthreads();
        s[tid] += t;
        __syncthreads();
    }
    if (tid < NBLK) g_bsum[tid] = s[tid] - v;  // exclusive
}

__global__ void scanfinal_kernel() {
    __shared__ int s[256];
    int tid = threadIdx.x;
    int i = blockIdx.x * 256 + tid;
    int v = (i < NV) ? g_deg[i] : 0;
    s[tid] = v;
    __syncthreads();
#pragma unroll
    for (int off = 1; off < 256; off <<= 1) {
        int t = (tid >= off) ? s[tid - off] : 0;
        __syncthreads();
        s[tid] += t;
        __syncthreads();
    }
    int ex = s[tid] - v + g_bsum[blockIdx.x];
    if (i < NV) {
        g_rowptr[i] = ex;
        g_pos[i] = ex;
        g_dinv[i] = rsqrtf((float)v + 1.f);
    }
    if (i == NV - 1) g_rowptr[NV] = ex + v;
}

// counting-sort edges by dst; pack {src, w} per edge
__global__ void sort_kernel(const int* __restrict__ src, const int* __restrict__ dst) {
    int e = blockIdx.x * blockDim.x + threadIdx.x;
    if (e >= EE) return;
    int s = src[e], d = dst[e];
    int p = atomicAdd(&g_pos[d], 1);
    float w = g_dinv[s] * g_dinv[d];
    g_epack[p] = make_int2(s, __float_as_int(w));
}

// ---------------- tensor-core GEMM: H16 = X @ W (bf16x3 split) ----------------
// FUSE_IN: X is computed on the fly as vertices @ W_in + b_in (layer 1).
// Otherwise X is read from fp16 activations (exact bf16 hi/lo resplit).
__device__ __forceinline__ void mma_bf16(float* c, const uint32_t* a,
                                         uint32_t b0, uint32_t b1) {
    asm volatile(
        "mma.sync.aligned.m16n8k16.row.col.f32.bf16.bf16.f32 "
        "{%0,%1,%2,%3}, {%4,%5,%6,%7}, {%8,%9}, {%0,%1,%2,%3};\n"
        : "+f"(c[0]), "+f"(c[1]), "+f"(c[2]), "+f"(c[3])
        : "r"(a[0]), "r"(a[1]), "r"(a[2]), "r"(a[3]), "r"(b0), "r"(b1));
}

#define BST 136          // smem row stride in bf16 elements
#define BSTW 68          // same, in 32-bit words
#define XTILE (128 * BST)
#define SMEM_BYTES (4 * XTILE * 2 + 512 * 4)   // 4 tiles bf16 + 512 floats for W_in/b_in

template <bool FUSE_IN>
__global__ void gemm_tc_kernel(const float* __restrict__ V,
                               const __half* __restrict__ X16,
                               const float* __restrict__ Wi,
                               const float* __restrict__ bi,
                               const float* __restrict__ W,
                               __half* __restrict__ H) {
    extern __shared__ __nv_bfloat16 sb[];
    __nv_bfloat16* Xh = sb;
    __nv_bfloat16* Xl = sb + XTILE;
    __nv_bfloat16* Wh = sb + 2 * XTILE;
    __nv_bfloat16* Wl = sb + 3 * XTILE;
    float* sWin = (float*)(sb + 4 * XTILE);  // [0,384): W_in, [384,512): b_in
    int t = threadIdx.x;
    int row0 = blockIdx.x * 128;

    // W [k][n] global -> transposed [n][k] split hi/lo in smem
#pragma unroll
    for (int i = 0; i < 64; i++) {
        int idx = i * 256 + t;
        int k = idx >> 7, n = idx & 127;
        float w = W[idx];
        __nv_bfloat16 wh = __float2bfloat16_rn(w);
        float rem = w - __bfloat162float(wh);
        Wh[n * BST + k] = wh;
        Wl[n * BST + k] = __float2bfloat16_rn(rem);
    }
    if (FUSE_IN) {
        for (int i = t; i < 512; i += 256)
            sWin[i] = (i < 384) ? Wi[i] : bi[i - 384];
        __syncthreads();   // X-tile builder below reads sWin
    }

    // X tile [128][128] -> split hi/lo row-major
#pragma unroll
    for (int i = 0; i < 16; i++) {
        int idx = i * 256 + t;
        int r = idx >> 5, q = idx & 31;
        int gr = row0 + r;
        float4 v = make_float4(0.f, 0.f, 0.f, 0.f);
        if (FUSE_IN) {
            float v0 = 0.f, v1 = 0.f, v2 = 0.f;
            if (gr < NV) {
                v0 = V[gr * 3 + 0]; v1 = V[gr * 3 + 1]; v2 = V[gr * 3 + 2];
            }
            int c = q * 4;
            float* pv = &v.x;
#pragma unroll
            for (int j = 0; j < 4; j++) {
                int cc = c + j;
                pv[j] = sWin[384 + cc] + v0 * sWin[cc] + v1 * sWin[128 + cc]
                        + v2 * sWin[256 + cc];
            }
        } else if (gr < NV) {
            uint2 u = *((const uint2*)X16 + gr * 32 + q);
            float2 f0 = __half22float2(*(__half2*)&u.x);
            float2 f1 = __half22float2(*(__half2*)&u.y);
            v = make_float4(f0.x, f0.y, f1.x, f1.y);
        }
        __nv_bfloat162 h0 = __floats2bfloat162_rn(v.x, v.y);
        __nv_bfloat162 h1 = __floats2bfloat162_rn(v.z, v.w);
        float2 hf0 = __bfloat1622float2(h0);
        float2 hf1 = __bfloat1622float2(h1);
        __nv_bfloat162 l0 = __floats2bfloat162_rn(v.x - hf0.x, v.y - hf0.y);
        __nv_bfloat162 l1 = __floats2bfloat162_rn(v.z - hf1.x, v.w - hf1.y);
        int base = r * BST + q * 4;
        *(__nv_bfloat162*)(Xh + base) = h0;
        *(__nv_bfloat162*)(Xh + base + 2) = h1;
        *(__nv_bfloat162*)(Xl + base) = l0;
        *(__nv_bfloat162*)(Xl + base + 2) = l1;
    }
    __syncthreads();

    int w = t >> 5, lane = t & 31;
    int wr = w >> 1, wc = w & 1;
    int g = lane >> 2, q4 = lane & 3;

    float acc[2][8][4];
#pragma unroll
    for (int mt = 0; mt < 2; mt++)
#pragma unroll
        for (int nt = 0; nt < 8; nt++)
#pragma unroll
            for (int j = 0; j < 4; j++) acc[mt][nt][j] = 0.f;

    const uint32_t* pXh = (const uint32_t*)Xh;
    const uint32_t* pXl = (const uint32_t*)Xl;
    const uint32_t* pWh = (const uint32_t*)Wh;
    const uint32_t* pWl = (const uint32_t*)Wl;

#pragma unroll
    for (int ks = 0; ks < 8; ks++) {
        int kw = ks * 8 + q4;
        uint32_t ah[2][4], al[2][4];
#pragma unroll
        for (int mt = 0; mt < 2; mt++) {
            int r = wr * 32 + mt * 16 + g;
            ah[mt][0] = pXh[r * BSTW + kw];
            ah[mt][1] = pXh[(r + 8) * BSTW + kw];
            ah[mt][2] = pXh[r * BSTW + kw + 4];
            ah[mt][3] = pXh[(r + 8) * BSTW + kw + 4];
            al[mt][0] = pXl[r * BSTW + kw];
            al[mt][1] = pXl[(r + 8) * BSTW + kw];
            al[mt][2] = pXl[r * BSTW + kw + 4];
            al[mt][3] = pXl[(r + 8) * BSTW + kw + 4];
        }
#pragma unroll
        for (int nt = 0; nt < 8; nt++) {
            int n = wc * 64 + nt * 8 + g;
            uint32_t bh0 = pWh[n * BSTW + kw];
            uint32_t bh1 = pWh[n * BSTW + kw + 4];
            uint32_t bl0 = pWl[n * BSTW + kw];
            uint32_t bl1 = pWl[n * BSTW + kw + 4];
#pragma unroll
            for (int mt = 0; mt < 2; mt++) {
                mma_bf16(acc[mt][nt], ah[mt], bh0, bh1);
                mma_bf16(acc[mt][nt], ah[mt], bl0, bl1);
                mma_bf16(acc[mt][nt], al[mt], bh0, bh1);
            }
        }
    }

    // epilogue: fp32 acc -> half2 stores
#pragma unroll
    for (int mt = 0; mt < 2; mt++) {
#pragma unroll
        for (int nt = 0; nt < 8; nt++) {
            int col = wc * 64 + nt * 8 + q4 * 2;
            int r = row0 + wr * 32 + mt * 16 + g;
            if (r < NV)
                *(__half2*)(H + r * HIDDEN + col) =
                    __floats2half2_rn(acc[mt][nt][0], acc[mt][nt][1]);
            int r2 = r + 8;
            if (r2 < NV)
                *(__half2*)(H + r2 * HIDDEN + col) =
                    __floats2half2_rn(acc[mt][nt][2], acc[mt][nt][3]);
        }
    }
}

// ---------------- aggregation: one warp per dst row, fp16 in/out, ReLU fused ----
__device__ __forceinline__ float4 h4_to_f4(uint2 u) {
    float2 f0 = __half22float2(*(__half2*)&u.x);
    float2 f1 = __half22float2(*(__half2*)&u.y);
    return make_float4(f0.x, f0.y, f1.x, f1.y);
}

__global__ void agg_kernel(const __half* __restrict__ H,
                           const float* __restrict__ bias,
                           __half* __restrict__ OUT) {
    int gw = (blockIdx.x * blockDim.x + threadIdx.x) >> 5;
    int lane = threadIdx.x & 31;
    if (gw >= NV) return;
    int beg = g_rowptr[gw], end = g_rowptr[gw + 1];
    float dd = g_dinv[gw];
    dd *= dd;
    const uint2* Hp = (const uint2*)H;   // 8B = 4 halfs per lane
    float4 h = h4_to_f4(Hp[gw * 32 + lane]);
    float4 b = *((const float4*)bias + lane);
    float4 acc = make_float4(h.x * dd + b.x, h.y * dd + b.y,
                             h.z * dd + b.z, h.w * dd + b.w);

    int e = beg;
    for (; e + 3 < end; e += 4) {
        int2 p0 = g_epack[e];
        int2 p1 = g_epack[e + 1];
        int2 p2 = g_epack[e + 2];
        int2 p3 = g_epack[e + 3];
        float4 v0 = h4_to_f4(Hp[p0.x * 32 + lane]);
        float4 v1 = h4_to_f4(Hp[p1.x * 32 + lane]);
        float4 v2 = h4_to_f4(Hp[p2.x * 32 + lane]);
        float4 v3 = h4_to_f4(Hp[p3.x * 32 + lane]);
        float w0 = __int_as_float(p0.y);
        float w1 = __int_as_float(p1.y);
        float w2 = __int_as_float(p2.y);
        float w3 = __int_as_float(p3.y);
        acc.x += w0 * v0.x + w1 * v1.x + w2 * v2.x + w3 * v3.x;
        acc.y += w0 * v0.y + w1 * v1.y + w2 * v2.y + w3 * v3.y;
        acc.z += w0 * v0.z + w1 * v1.z + w2 * v2.z + w3 * v3.z;
        acc.w += w0 * v0.w + w1 * v1.w + w2 * v2.w + w3 * v3.w;
    }
    for (; e < end; e++) {
        int2 p = g_epack[e];
        float w = __int_as_float(p.y);
        float4 v = h4_to_f4(Hp[p.x * 32 + lane]);
        acc.x += w * v.x; acc.y += w * v.y;
        acc.z += w * v.z; acc.w += w * v.w;
    }
    // ReLU + fp16 store
    uint2 o;
    *(__half2*)&o.x = __floats2half2_rn(fmaxf(acc.x, 0.f), fmaxf(acc.y, 0.f));
    *(__half2*)&o.y = __floats2half2_rn(fmaxf(acc.z, 0.f), fmaxf(acc.w, 0.f));
    *((uint2*)OUT + gw * 32 + lane) = o;
}

// ---------------- pooling over sorted batch (fp16 in, already ReLU'd) ----------
__global__ void pool_kernel(const __half* __restrict__ X, const int* __restrict__ batch) {
    int c = threadIdx.x;
    int row0 = blockIdx.x * POOL_ROWS;
    if (row0 >= NV) return;
    int rend = min(row0 + POOL_ROWS, NV);
    float acc = 0.f;
    int cur = batch[row0];
    int runstart = row0;
    for (int r = row0; r < rend; r++) {
        int b = batch[r];
        if (b != cur) {
            atomicAdd(&g_summ[cur * HIDDEN + c], acc);
            if (c == 0) atomicAdd(&g_cnt[cur], (float)(r - runstart));
            acc = 0.f; cur = b; runstart = r;
        }
        acc += __half2float(X[(long long)r * HIDDEN + c]);
    }
    atomicAdd(&g_summ[cur * HIDDEN + c], acc);
    if (c == 0) atomicAdd(&g_cnt[cur], (float)(rend - runstart));
}

// ---------------- head: pooled @ W_out + b_out, layernorm ----------------
__global__ void final_kernel(const float* __restrict__ Wo, const float* __restrict__ bo,
                             const float* __restrict__ gamma, const float* __restrict__ beta,
                             float* __restrict__ out) {
    __shared__ float p[HIDDEN];
    __shared__ float rs[DMODEL];
    __shared__ float rq[DMODEL];
    int b = blockIdx.x, c = threadIdx.x;
    if (c < HIDDEN) {
        float cnt = fmaxf(g_cnt[b], 1.f);
        p[c] = g_summ[b * HIDDEN + c] / cnt;
    }
    __syncthreads();
    float y = bo[c];
#pragma unroll 8
    for (int k = 0; k < HIDDEN; k++) y += p[k] * Wo[k * DMODEL + c];
    rs[c] = y;
    rq[c] = y * y;
    __syncthreads();
    for (int s = DMODEL / 2; s > 0; s >>= 1) {
        if (c < s) { rs[c] += rs[c + s]; rq[c] += rq[c + s]; }
        __syncthreads();
    }
    float mu = rs[0] / (float)DMODEL;
    float var = rq[0] / (float)DMODEL - mu * mu;
    out[b * DMODEL + c] = (y - mu) * rsqrtf(var + EPSV) * gamma[c] + beta[c];
}

// ---------------- launch ----------------
extern "C" void kernel_launch(void* const* d_in, const int* in_sizes, int n_in,
                              void* d_out, int out_size) {
    const float* vertices = (const float*)d_in[0];
    const int*   eidx     = (const int*)d_in[1];
    const int*   batch    = (const int*)d_in[2];
    const float* W_in     = (const float*)d_in[3];
    const float* b_in     = (const float*)d_in[4];
    const float* W1       = (const float*)d_in[5];
    const float* b1       = (const float*)d_in[6];
    const float* W2       = (const float*)d_in[7];
    const float* b2       = (const float*)d_in[8];
    const float* W3       = (const float*)d_in[9];
    const float* b3       = (const float*)d_in[10];
    const float* W_out    = (const float*)d_in[11];
    const float* b_out    = (const float*)d_in[12];
    const float* gamma    = (const float*)d_in[13];
    const float* beta     = (const float*)d_in[14];
    const int* src = eidx;
    const int* dst = eidx + EE;
    float* out = (float*)d_out;

    __half *ph, *pxa, *pxb;
    cudaGetSymbolAddress((void**)&ph, g_h16);
    cudaGetSymbolAddress((void**)&pxa, g_x16a);
    cudaGetSymbolAddress((void**)&pxb, g_x16b);

    cudaFuncSetAttribute(gemm_tc_kernel<true>,  cudaFuncAttributeMaxDynamicSharedMemorySize, SMEM_BYTES);
    cudaFuncSetAttribute(gemm_tc_kernel<false>, cudaFuncAttributeMaxDynamicSharedMemorySize, SMEM_BYTES);

    int nb256 = (NV + 255) / 256;
    zero_kernel<<<nb256, 256>>>();
    deg_kernel<<<(EE + 255) / 256, 256>>>(dst);
    blocksum_kernel<<<NBLK, 256>>>();
    scanbsum_kernel<<<1, 512>>>();
    scanfinal_kernel<<<NBLK, 256>>>();
    sort_kernel<<<(EE + 255) / 256, 256>>>(src, dst);

    int gblocks = (NV + 127) / 128;
    int ablocks = (int)(((long long)NV * 32 + 255) / 256);

    // layer 1: input projection fused into GEMM
    gemm_tc_kernel<true><<<gblocks, 256, SMEM_BYTES>>>(vertices, (const __half*)0,
                                                       W_in, b_in, W1, ph);
    agg_kernel<<<ablocks, 256>>>(ph, b1, pxa);

    gemm_tc_kernel<false><<<gblocks, 256, SMEM_BYTES>>>((const float*)0, pxa,
                                                        (const float*)0, (const float*)0, W2, ph);
    agg_kernel<<<ablocks, 256>>>(ph, b2, pxb);

    gemm_tc_kernel<false><<<gblocks, 256, SMEM_BYTES>>>((const float*)0, pxb,
                                                        (const float*)0, (const float*)0, W3, ph);
    agg_kernel<<<ablocks, 256>>>(ph, b3, pxa);

    pool_kernel<<<(NV + POOL_ROWS - 1) / POOL_ROWS, HIDDEN>>>(pxa, batch);
    final_kernel<<<BB, DMODEL>>>(W_out, b_out, gamma, beta, out);
}

// round 8
// speedup vs baseline: 5.3471x; 1.0845x over previous
#include <cuda_runtime.h>
#include <cuda_bf16.h>
#include <cuda_fp16.h>
#include <cstdint>

#define NV 100000
#define EE 1600000
#define BB 64
#define HIDDEN 128
#define DMODEL 256
#define EPSV 1e-5f
#define POOL_ROWS 128
#define NBLK ((NV + 255) / 256)   // 391 scan blocks

// ---------------- scratch (static device globals; no allocation) ----------------
__device__ __half g_h16[NV * HIDDEN];   // pre-aggregation features (fp16)
__device__ __half g_x16a[NV * HIDDEN];  // activation ping (fp16)
__device__ __half g_x16b[NV * HIDDEN];  // activation pong (fp16)
__device__ float g_dinv[NV];            // deg^{-1/2}
__device__ int   g_deg[NV];             // in-degree
__device__ int   g_rowptr[NV + 1];      // CSR offsets (by dst)
__device__ int   g_pos[NV];             // running insert positions for sort
__device__ unsigned long long g_desc[NBLK];  // decoupled-lookback descriptors
__device__ int2  g_epack[EE];           // sorted edges: {src, bits(w)}
__device__ float g_summ[BB * HIDDEN];   // pooled sums
__device__ float g_cnt[BB];             // pooled counts

// ---------------- setup kernels ----------------
__global__ void zero_kernel() {
    int i = blockIdx.x * blockDim.x + threadIdx.x;
    if (i < NV) g_deg[i] = 0;
    if (i < NBLK) g_desc[i] = 0ULL;
    if (i < BB * HIDDEN) g_summ[i] = 0.f;
    if (i < BB) g_cnt[i] = 0.f;
}

__global__ void deg_kernel(const int4* __restrict__ dst4) {
    int e = blockIdx.x * blockDim.x + threadIdx.x;
    if (e < EE / 4) {
        int4 d = dst4[e];
        atomicAdd(&g_deg[d.x], 1);
        atomicAdd(&g_deg[d.y], 1);
        atomicAdd(&g_deg[d.z], 1);
        atomicAdd(&g_deg[d.w], 1);
    }
}

// --- single-pass decoupled-lookback exclusive scan of g_deg ---
// g_desc[b] = state<<32 | value.  state: 0=invalid, 1=aggregate, 2=prefix.
__global__ void scan_kernel() {
    __shared__ int s[256];
    __shared__ int sh_ex;
    int tid = threadIdx.x;
    int b = blockIdx.x;
    int i = b * 256 + tid;
    int v = (i < NV) ? g_deg[i] : 0;
    s[tid] = v;
    __syncthreads();
#pragma unroll
    for (int off = 1; off < 256; off <<= 1) {
        int t = (tid >= off) ? s[tid - off] : 0;
        __syncthreads();
        s[tid] += t;
        __syncthreads();
    }
    int incl = s[tid];
    int total = s[255];

    if (tid == 0) {
        unsigned long long ex = 0;
        if (b > 0) {
            // publish aggregate so successors can pass us
            atomicExch(&g_desc[b], (1ULL << 32) | (unsigned int)total);
            int j = b - 1;
            while (true) {
                unsigned long long d = atomicAdd(&g_desc[j], 0ULL);
                unsigned int st = (unsigned int)(d >> 32);
                if (st == 2u) { ex += (unsigned int)d; break; }
                if (st == 1u) { ex += (unsigned int)d; j--; }
                // st == 0: spin (block 0 publishes PREFIX immediately -> progress)
            }
        }
        atomicExch(&g_desc[b], (2ULL << 32) | (unsigned int)(ex + (unsigned int)total));
        sh_ex = (int)ex;
    }
    __syncthreads();
    int excl = sh_ex + incl - v;
    if (i < NV) {
        g_rowptr[i] = excl;
        g_pos[i] = excl;
        g_dinv[i] = rsqrtf((float)v + 1.f);
    }
    if (i == NV - 1) g_rowptr[NV] = excl + v;
}

// counting-sort edges by dst; pack {src, w} per edge
__global__ void sort_kernel(const int* __restrict__ src, const int* __restrict__ dst) {
    int e = blockIdx.x * blockDim.x + threadIdx.x;
    if (e >= EE) return;
    int s = src[e], d = dst[e];
    int p = atomicAdd(&g_pos[d], 1);
    float w = g_dinv[s] * g_dinv[d];
    g_epack[p] = make_int2(s, __float_as_int(w));
}

// ---------------- tensor-core GEMM: H16 = X @ W (bf16 split) ----------------
// FUSE_IN: X computed on the fly as vertices @ W_in + b_in (layer 1, fp32 -> hi/lo).
// XLO: carry the X low-order bf16 tile + third MMA (needed only when X is fp32).
__device__ __forceinline__ void mma_bf16(float* c, const uint32_t* a,
                                         uint32_t b0, uint32_t b1) {
    asm volatile(
        "mma.sync.aligned.m16n8k16.row.col.f32.bf16.bf16.f32 "
        "{%0,%1,%2,%3}, {%4,%5,%6,%7}, {%8,%9}, {%0,%1,%2,%3};\n"
        : "+f"(c[0]), "+f"(c[1]), "+f"(c[2]), "+f"(c[3])
        : "r"(a[0]), "r"(a[1]), "r"(a[2]), "r"(a[3]), "r"(b0), "r"(b1));
}

#define BST 136          // smem row stride in bf16 elements
#define BSTW 68          // same, in 32-bit words
#define XTILE (128 * BST)
#define SMEM_L1 (4 * XTILE * 2 + 512 * 4)   // Xh,Xl,Wh,Wl + W_in/b_in floats
#define SMEM_L23 (3 * XTILE * 2)            // Xh,Wh,Wl

template <bool FUSE_IN, bool XLO>
__global__ void gemm_tc_kernel(const float* __restrict__ V,
                               const __half* __restrict__ X16,
                               const float* __restrict__ Wi,
                               const float* __restrict__ bi,
                               const float* __restrict__ W,
                               __half* __restrict__ H) {
    extern __shared__ __nv_bfloat16 sb[];
    __nv_bfloat16* Xh = sb;
    __nv_bfloat16* Xl = sb + XTILE;                    // only used when XLO
    __nv_bfloat16* Wh = sb + (XLO ? 2 : 1) * XTILE;
    __nv_bfloat16* Wl = sb + (XLO ? 3 : 2) * XTILE;
    float* sWin = (float*)(sb + 4 * XTILE);            // only used when FUSE_IN
    int t = threadIdx.x;
    int row0 = blockIdx.x * 128;

    // W [k][n] global -> transposed [n][k] split hi/lo in smem
#pragma unroll
    for (int i = 0; i < 64; i++) {
        int idx = i * 256 + t;
        int k = idx >> 7, n = idx & 127;
        float w = W[idx];
        __nv_bfloat16 wh = __float2bfloat16_rn(w);
        float rem = w - __bfloat162float(wh);
        Wh[n * BST + k] = wh;
        Wl[n * BST + k] = __float2bfloat16_rn(rem);
    }
    if (FUSE_IN) {
        for (int i = t; i < 512; i += 256)
            sWin[i] = (i < 384) ? Wi[i] : bi[i - 384];
        __syncthreads();   // X-tile builder below reads sWin
    }

    // X tile [128][128] -> bf16 (hi [, lo]) row-major
#pragma unroll
    for (int i = 0; i < 16; i++) {
        int idx = i * 256 + t;
        int r = idx >> 5, q = idx & 31;
        int gr = row0 + r;
        float4 v = make_float4(0.f, 0.f, 0.f, 0.f);
        if (FUSE_IN) {
            float v0 = 0.f, v1 = 0.f, v2 = 0.f;
            if (gr < NV) {
                v0 = V[gr * 3 + 0]; v1 = V[gr * 3 + 1]; v2 = V[gr * 3 + 2];
            }
            int c = q * 4;
            float* pv = &v.x;
#pragma unroll
            for (int j = 0; j < 4; j++) {
                int cc = c + j;
                pv[j] = sWin[384 + cc] + v0 * sWin[cc] + v1 * sWin[128 + cc]
                        + v2 * sWin[256 + cc];
            }
        } else if (gr < NV) {
            uint2 u = *((const uint2*)X16 + gr * 32 + q);
            float2 f0 = __half22float2(*(__half2*)&u.x);
            float2 f1 = __half22float2(*(__half2*)&u.y);
            v = make_float4(f0.x, f0.y, f1.x, f1.y);
        }
        __nv_bfloat162 h0 = __floats2bfloat162_rn(v.x, v.y);
        __nv_bfloat162 h1 = __floats2bfloat162_rn(v.z, v.w);
        int base = r * BST + q * 4;
        *(__nv_bfloat162*)(Xh + base) = h0;
        *(__nv_bfloat162*)(Xh + base + 2) = h1;
        if (XLO) {
            float2 hf0 = __bfloat1622float2(h0);
            float2 hf1 = __bfloat1622float2(h1);
            *(__nv_bfloat162*)(Xl + base) = __floats2bfloat162_rn(v.x - hf0.x, v.y - hf0.y);
            *(__nv_bfloat162*)(Xl + base + 2) = __floats2bfloat162_rn(v.z - hf1.x, v.w - hf1.y);
        }
    }
    __syncthreads();

    int w = t >> 5, lane = t & 31;
    int wr = w >> 1, wc = w & 1;
    int g = lane >> 2, q4 = lane & 3;

    float acc[2][8][4];
#pragma unroll
    for (int mt = 0; mt < 2; mt++)
#pragma unroll
        for (int nt = 0; nt < 8; nt++)
#pragma unroll
            for (int j = 0; j < 4; j++) acc[mt][nt][j] = 0.f;

    const uint32_t* pXh = (const uint32_t*)Xh;
    const uint32_t* pXl = (const uint32_t*)Xl;
    const uint32_t* pWh = (const uint32_t*)Wh;
    const uint32_t* pWl = (const uint32_t*)Wl;

#pragma unroll
    for (int ks = 0; ks < 8; ks++) {
        int kw = ks * 8 + q4;
        uint32_t ah[2][4], al[2][4];
#pragma unroll
        for (int mt = 0; mt < 2; mt++) {
            int r = wr * 32 + mt * 16 + g;
            ah[mt][0] = pXh[r * BSTW + kw];
            ah[mt][1] = pXh[(r + 8) * BSTW + kw];
            ah[mt][2] = pXh[r * BSTW + kw + 4];
            ah[mt][3] = pXh[(r + 8) * BSTW + kw + 4];
            if (XLO) {
                al[mt][0] = pXl[r * BSTW + kw];
                al[mt][1] = pXl[(r + 8) * BSTW + kw];
                al[mt][2] = pXl[r * BSTW + kw + 4];
                al[mt][3] = pXl[(r + 8) * BSTW + kw + 4];
            }
        }
#pragma unroll
        for (int nt = 0; nt < 8; nt++) {
            int n = wc * 64 + nt * 8 + g;
            uint32_t bh0 = pWh[n * BSTW + kw];
            uint32_t bh1 = pWh[n * BSTW + kw + 4];
            uint32_t bl0 = pWl[n * BSTW + kw];
            uint32_t bl1 = pWl[n * BSTW + kw + 4];
#pragma unroll
            for (int mt = 0; mt < 2; mt++) {
                mma_bf16(acc[mt][nt], ah[mt], bh0, bh1);
                mma_bf16(acc[mt][nt], ah[mt], bl0, bl1);
                if (XLO) mma_bf16(acc[mt][nt], al[mt], bh0, bh1);
            }
        }
    }

    // epilogue: fp32 acc -> half2 stores
#pragma unroll
    for (int mt = 0; mt < 2; mt++) {
#pragma unroll
        for (int nt = 0; nt < 8; nt++) {
            int col = wc * 64 + nt * 8 + q4 * 2;
            int r = row0 + wr * 32 + mt * 16 + g;
            if (r < NV)
                *(__half2*)(H + r * HIDDEN + col) =
                    __floats2half2_rn(acc[mt][nt][0], acc[mt][nt][1]);
            int r2 = r + 8;
            if (r2 < NV)
                *(__half2*)(H + r2 * HIDDEN + col) =
                    __floats2half2_rn(acc[mt][nt][2], acc[mt][nt][3]);
        }
    }
}

// ---------------- aggregation: one warp per dst row, fp16 in/out, ReLU fused ----
__device__ __forceinline__ float4 h4_to_f4(uint2 u) {
    float2 f0 = __half22float2(*(__half2*)&u.x);
    float2 f1 = __half22float2(*(__half2*)&u.y);
    return make_float4(f0.x, f0.y, f1.x, f1.y);
}

__global__ void agg_kernel(const __half* __restrict__ H,
                           const float* __restrict__ bias,
                           __half* __restrict__ OUT) {
    int gw = (blockIdx.x * blockDim.x + threadIdx.x) >> 5;
    int lane = threadIdx.x & 31;
    if (gw >= NV) return;
    int beg = g_rowptr[gw], end = g_rowptr[gw + 1];
    float dd = g_dinv[gw];
    dd *= dd;
    const uint2* Hp = (const uint2*)H;   // 8B = 4 halfs per lane
    float4 h = h4_to_f4(Hp[gw * 32 + lane]);
    float4 b = *((const float4*)bias + lane);
    float4 acc = make_float4(h.x * dd + b.x, h.y * dd + b.y,
                             h.z * dd + b.z, h.w * dd + b.w);

    int e = beg;
    for (; e + 3 < end; e += 4) {
        int2 p0 = g_epack[e];
        int2 p1 = g_epack[e + 1];
        int2 p2 = g_epack[e + 2];
        int2 p3 = g_epack[e + 3];
        float4 v0 = h4_to_f4(Hp[p0.x * 32 + lane]);
        float4 v1 = h4_to_f4(Hp[p1.x * 32 + lane]);
        float4 v2 = h4_to_f4(Hp[p2.x * 32 + lane]);
        float4 v3 = h4_to_f4(Hp[p3.x * 32 + lane]);
        float w0 = __int_as_float(p0.y);
        float w1 = __int_as_float(p1.y);
        float w2 = __int_as_float(p2.y);
        float w3 = __int_as_float(p3.y);
        acc.x += w0 * v0.x + w1 * v1.x + w2 * v2.x + w3 * v3.x;
        acc.y += w0 * v0.y + w1 * v1.y + w2 * v2.y + w3 * v3.y;
        acc.z += w0 * v0.z + w1 * v1.z + w2 * v2.z + w3 * v3.z;
        acc.w += w0 * v0.w + w1 * v1.w + w2 * v2.w + w3 * v3.w;
    }
    for (; e < end; e++) {
        int2 p = g_epack[e];
        float w = __int_as_float(p.y);
        float4 v = h4_to_f4(Hp[p.x * 32 + lane]);
        acc.x += w * v.x; acc.y += w * v.y;
        acc.z += w * v.z; acc.w += w * v.w;
    }
    // ReLU + fp16 store
    uint2 o;
    *(__half2*)&o.x = __floats2half2_rn(fmaxf(acc.x, 0.f), fmaxf(acc.y, 0.f));
    *(__half2*)&o.y = __floats2half2_rn(fmaxf(acc.z, 0.f), fmaxf(acc.w, 0.f));
    *((uint2*)OUT + gw * 32 + lane) = o;
}

// ---------------- pooling over sorted batch (fp16 in, already ReLU'd) ----------
__global__ void pool_kernel(const __half* __restrict__ X, const int* __restrict__ batch) {
    int c = threadIdx.x;
    int row0 = blockIdx.x * POOL_ROWS;
    if (row0 >= NV) return;
    int rend = min(row0 + POOL_ROWS, NV);
    float acc = 0.f;
    int cur = batch[row0];
    int runstart = row0;
    for (int r = row0; r < rend; r++) {
        int b = batch[r];
        if (b != cur) {
            atomicAdd(&g_summ[cur * HIDDEN + c], acc);
            if (c == 0) atomicAdd(&g_cnt[cur], (float)(r - runstart));
            acc = 0.f; cur = b; runstart = r;
        }
        acc += __half2float(X[(long long)r * HIDDEN + c]);
    }
    atomicAdd(&g_summ[cur * HIDDEN + c], acc);
    if (c == 0) atomicAdd(&g_cnt[cur], (float)(rend - runstart));
}

// ---------------- head: pooled @ W_out + b_out, layernorm ----------------
__global__ void final_kernel(const float* __restrict__ Wo, const float* __restrict__ bo,
                             const float* __restrict__ gamma, const float* __restrict__ beta,
                             float* __restrict__ out) {
    __shared__ float p[HIDDEN];
    __shared__ float rs[DMODEL];
    __shared__ float rq[DMODEL];
    int b = blockIdx.x, c = threadIdx.x;
    if (c < HIDDEN) {
        float cnt = fmaxf(g_cnt[b], 1.f);
        p[c] = g_summ[b * HIDDEN + c] / cnt;
    }
    __syncthreads();
    float y = bo[c];
#pragma unroll 8
    for (int k = 0; k < HIDDEN; k++) y += p[k] * Wo[k * DMODEL + c];
    rs[c] = y;
    rq[c] = y * y;
    __syncthreads();
    for (int s = DMODEL / 2; s > 0; s >>= 1) {
        if (c < s) { rs[c] += rs[c + s]; rq[c] += rq[c + s]; }
        __syncthreads();
    }
    float mu = rs[0] / (float)DMODEL;
    float var = rq[0] / (float)DMODEL - mu * mu;
    out[b * DMODEL + c] = (y - mu) * rsqrtf(var + EPSV) * gamma[c] + beta[c];
}

// ---------------- launch ----------------
extern "C" void kernel_launch(void* const* d_in, const int* in_sizes, int n_in,
                              void* d_out, int out_size) {
    const float* vertices = (const float*)d_in[0];
    const int*   eidx     = (const int*)d_in[1];
    const int*   batch    = (const int*)d_in[2];
    const float* W_in     = (const float*)d_in[3];
    const float* b_in     = (const float*)d_in[4];
    const float* W1       = (const float*)d_in[5];
    const float* b1       = (const float*)d_in[6];
    const float* W2       = (const float*)d_in[7];
    const float* b2       = (const float*)d_in[8];
    const float* W3       = (const float*)d_in[9];
    const float* b3       = (const float*)d_in[10];
    const float* W_out    = (const float*)d_in[11];
    const float* b_out    = (const float*)d_in[12];
    const float* gamma    = (const float*)d_in[13];
    const float* beta     = (const float*)d_in[14];
    const int* src = eidx;
    const int* dst = eidx + EE;
    float* out = (float*)d_out;

    __half *ph, *pxa, *pxb;
    cudaGetSymbolAddress((void**)&ph, g_h16);
    cudaGetSymbolAddress((void**)&pxa, g_x16a);
    cudaGetSymbolAddress((void**)&pxb, g_x16b);

    cudaFuncSetAttribute((gemm_tc_kernel<true, true>),
                         cudaFuncAttributeMaxDynamicSharedMemorySize, SMEM_L1);
    cudaFuncSetAttribute((gemm_tc_kernel<false, false>),
                         cudaFuncAttributeMaxDynamicSharedMemorySize, SMEM_L23);

    int nb256 = (NV + 255) / 256;
    zero_kernel<<<nb256, 256>>>();
    deg_kernel<<<(EE / 4 + 255) / 256, 256>>>((const int4*)dst);
    scan_kernel<<<NBLK, 256>>>();
    sort_kernel<<<(EE + 255) / 256, 256>>>(src, dst);

    int gblocks = (NV + 127) / 128;
    int ablocks = (int)(((long long)NV * 32 + 255) / 256);

    // layer 1: input projection fused into GEMM (fp32 X -> full hi/lo split)
    gemm_tc_kernel<true, true><<<gblocks, 256, SMEM_L1>>>(vertices, (const __half*)0,
                                                          W_in, b_in, W1, ph);
    agg_kernel<<<ablocks, 256>>>(ph, b1, pxa);

    // layers 2,3: fp16 X -> hi-only (2 MMAs)
    gemm_tc_kernel<false, false><<<gblocks, 256, SMEM_L23>>>((const float*)0, pxa,
                                                             (const float*)0, (const float*)0, W2, ph);
    agg_kernel<<<ablocks, 256>>>(ph, b2, pxb);

    gemm_tc_kernel<false, false><<<gblocks, 256, SMEM_L23>>>((const float*)0, pxb,
                                                             (const float*)0, (const float*)0, W3, ph);
    agg_kernel<<<ablocks, 256>>>(ph, b3, pxa);

    pool_kernel<<<(NV + POOL_ROWS - 1) / POOL_ROWS, HIDDEN>>>(pxa, batch);
    final_kernel<<<BB, DMODEL>>>(W_out, b_out, gamma, beta, out);
}